// round 12
// baseline (speedup 1.0000x reference)
#include <cuda_runtime.h>
#include <cstdint>
#include <cstddef>

// Problem constants
#define E_EDGES 100000
#define N_NODES 25000
#define HID 512
#define NG 2048
#define FN 133
#define FE 14
#define KE2N 645

// ---------------------------------------------------------------------------
// Scratch (device globals)
// ---------------------------------------------------------------------------
__device__ float g_h0[(size_t)E_EDGES * HID];
__device__ float g_hA[(size_t)E_EDGES * HID];
__device__ float g_hB[(size_t)E_EDGES * HID];   // first 25k rows reused as X' in edge phase
__device__ float g_aA[(size_t)N_NODES * HID];
__device__ float g_aB[(size_t)N_NODES * HID];
__device__ float g_pool[(size_t)NG * HID];

// ---------------------------------------------------------------------------
// Helpers
// ---------------------------------------------------------------------------
__device__ __forceinline__ void red_add_v4(float* addr, float x, float y, float z, float w) {
    asm volatile("red.global.add.v4.f32 [%0], {%1,%2,%3,%4};"
                 :: "l"(addr), "f"(x), "f"(y), "f"(z), "f"(w) : "memory");
}

// ---------------------------------------------------------------------------
// Node projection: X'[n] = x[n] @ W1 + b   (M=25000, K=133 pad 136, N=512)
// ---------------------------------------------------------------------------
__global__ __launch_bounds__(256, 2)
void xproj_kernel(const float* __restrict__ x, const float* __restrict__ W,
                  const float* __restrict__ bias, float* __restrict__ Xp)
{
    __shared__ float As[8][132];
    __shared__ float Bs[8][128];
    const int tid = threadIdx.x;
    const int tx = tid & 15, ty = tid >> 4;
    const int bm = blockIdx.y * 128;
    const int bn = blockIdx.x * 128;

    const int arow = tid >> 1;
    const int ac4  = (tid & 1) * 4;
    const int am   = bm + arow;
    const bool aValid = (am < N_NODES);

    const int brow = tid >> 5;
    const int bc4  = (tid & 31) * 4;

    float acc[8][8];
    #pragma unroll
    for (int i = 0; i < 8; i++)
        #pragma unroll
        for (int j = 0; j < 8; j++) acc[i][j] = 0.f;

    for (int k0 = 0; k0 < 136; k0 += 8) {
        #pragma unroll
        for (int i = 0; i < 4; i++) {
            int k = k0 + ac4 + i;
            float v = 0.f;
            if (aValid && k < FN) v = x[(size_t)am * FN + k];
            As[ac4 + i][arow] = v;
        }
        int kRow = k0 + brow;
        float4 bv = make_float4(0.f, 0.f, 0.f, 0.f);
        if (kRow < FN) bv = *(const float4*)(W + (size_t)kRow * HID + bn + bc4);
        *(float4*)&Bs[brow][bc4] = bv;
        __syncthreads();

        #pragma unroll
        for (int kk = 0; kk < 8; kk++) {
            float ar[8], br[8];
            #pragma unroll
            for (int i = 0; i < 8; i++) ar[i] = As[kk][ty * 8 + i];
            #pragma unroll
            for (int j = 0; j < 8; j++) br[j] = Bs[kk][tx * 8 + j];
            #pragma unroll
            for (int i = 0; i < 8; i++)
                #pragma unroll
                for (int j = 0; j < 8; j++) acc[i][j] += ar[i] * br[j];
        }
        __syncthreads();
    }

    const int n0 = bn + tx * 8;
    float bres[8];
    #pragma unroll
    for (int j = 0; j < 8; j++) bres[j] = bias[n0 + j];

    #pragma unroll
    for (int i = 0; i < 8; i++) {
        int m = bm + ty * 8 + i;
        if (m < N_NODES) {
            float* xo = Xp + (size_t)m * HID + n0;
            *(float4*)(xo)     = make_float4(acc[i][0] + bres[0], acc[i][1] + bres[1],
                                             acc[i][2] + bres[2], acc[i][3] + bres[3]);
            *(float4*)(xo + 4) = make_float4(acc[i][4] + bres[4], acc[i][5] + bres[5],
                                             acc[i][6] + bres[6], acc[i][7] + bres[7]);
        }
    }
}

// ---------------------------------------------------------------------------
// Edge combine: h0[e] = relu(X'[row[e]] + ea[e] @ W2);  aA[col[e]] += h0[e]
// ---------------------------------------------------------------------------
__global__ __launch_bounds__(256)
void edge_combine_kernel(const float* __restrict__ Xp, const float* __restrict__ ea,
                         const float* __restrict__ W2, const int* __restrict__ ei)
{
    __shared__ float W2s[FE * HID];   // 28 KB
    const int tid = threadIdx.x;
    for (int i = tid; i < FE * HID; i += 256) W2s[i] = W2[i];
    __syncthreads();

    const int w = tid >> 5;
    const int lane = tid & 31;
    const int e = blockIdx.x * 8 + w;

    const int r = ei[e];
    const int c = ei[E_EDGES + e];
    float ear[FE];
    #pragma unroll
    for (int k = 0; k < FE; k++) ear[k] = ea[(size_t)e * FE + k];

    const float* xp = Xp + (size_t)r * HID;
    float* h0p = g_h0 + (size_t)e * HID;
    float* aop = g_aA + (size_t)c * HID;

    #pragma unroll
    for (int i = 0; i < 4; i++) {
        const int c4 = i * 128 + lane * 4;
        float4 acc = *(const float4*)(xp + c4);
        #pragma unroll
        for (int k = 0; k < FE; k++) {
            float4 w4 = *(const float4*)(W2s + k * HID + c4);
            acc.x += ear[k] * w4.x;  acc.y += ear[k] * w4.y;
            acc.z += ear[k] * w4.z;  acc.w += ear[k] * w4.w;
        }
        acc.x = acc.x > 0.f ? acc.x : 0.f;
        acc.y = acc.y > 0.f ? acc.y : 0.f;
        acc.z = acc.z > 0.f ? acc.z : 0.f;
        acc.w = acc.w > 0.f ? acc.w : 0.f;
        *(float4*)(h0p + c4) = acc;
        red_add_v4(aop + c4, acc.x, acc.y, acc.z, acc.w);
    }
}

// ---------------------------------------------------------------------------
// Conv layer (R10-proven, 128x128, 256 threads):
//   h_out[e] = relu((a[row[e]] - h[e^1]) @ W + b + h0[e]); a_out[col[e]] += h_out
// ---------------------------------------------------------------------------
__global__ __launch_bounds__(256, 2)
void conv_kernel(const float* __restrict__ h_in, const float* __restrict__ a_in,
                 float* __restrict__ h_out, float* __restrict__ a_out,
                 const float* __restrict__ W, const float* __restrict__ bias,
                 const int* __restrict__ ei)
{
    __shared__ float As[8][132];
    __shared__ float Bs[8][128];
    const int tid = threadIdx.x;
    const int tx = tid & 15, ty = tid >> 4;
    const int bm = blockIdx.y * 128;
    const int bn = blockIdx.x * 128;

    const int arow = tid >> 1;
    const int ac4  = (tid & 1) * 4;
    const int am   = bm + arow;
    const bool aValid = (am < E_EDGES);
    const int r = aValid ? ei[am] : 0;
    const float* a_src = a_in + (size_t)r * HID + ac4;
    const float* h_src = h_in + (size_t)(am ^ 1) * HID + ac4;

    const int brow = tid >> 5;
    const int bc4  = (tid & 31) * 4;
    const float* w_src = W + (size_t)brow * HID + bn + bc4;

    float acc[8][8];
    #pragma unroll
    for (int i = 0; i < 8; i++)
        #pragma unroll
        for (int j = 0; j < 8; j++) acc[i][j] = 0.f;

    for (int k0 = 0; k0 < HID; k0 += 8) {
        float4 av = make_float4(0.f, 0.f, 0.f, 0.f);
        if (aValid) {
            float4 aa = *(const float4*)(a_src + k0);
            float4 hh = *(const float4*)(h_src + k0);
            av.x = aa.x - hh.x; av.y = aa.y - hh.y;
            av.z = aa.z - hh.z; av.w = aa.w - hh.w;
        }
        As[ac4 + 0][arow] = av.x;
        As[ac4 + 1][arow] = av.y;
        As[ac4 + 2][arow] = av.z;
        As[ac4 + 3][arow] = av.w;
        *(float4*)&Bs[brow][bc4] = *(const float4*)(w_src + (size_t)k0 * HID);
        __syncthreads();

        #pragma unroll
        for (int kk = 0; kk < 8; kk++) {
            float ar[8], br[8];
            #pragma unroll
            for (int i = 0; i < 8; i++) ar[i] = As[kk][ty * 8 + i];
            #pragma unroll
            for (int j = 0; j < 8; j++) br[j] = Bs[kk][tx * 8 + j];
            #pragma unroll
            for (int i = 0; i < 8; i++)
                #pragma unroll
                for (int j = 0; j < 8; j++) acc[i][j] += ar[i] * br[j];
        }
        __syncthreads();
    }

    const int n0 = bn + tx * 8;
    float bres[8];
    #pragma unroll
    for (int j = 0; j < 8; j++) bres[j] = bias[n0 + j];

    #pragma unroll
    for (int i = 0; i < 8; i++) {
        int m = bm + ty * 8 + i;
        if (m < E_EDGES) {
            const float* h0r = g_h0 + (size_t)m * HID + n0;
            float4 r0 = *(const float4*)(h0r);
            float4 r1 = *(const float4*)(h0r + 4);
            float v[8];
            v[0] = acc[i][0] + bres[0] + r0.x; v[1] = acc[i][1] + bres[1] + r0.y;
            v[2] = acc[i][2] + bres[2] + r0.z; v[3] = acc[i][3] + bres[3] + r0.w;
            v[4] = acc[i][4] + bres[4] + r1.x; v[5] = acc[i][5] + bres[5] + r1.y;
            v[6] = acc[i][6] + bres[6] + r1.z; v[7] = acc[i][7] + bres[7] + r1.w;
            #pragma unroll
            for (int j = 0; j < 8; j++) v[j] = v[j] > 0.f ? v[j] : 0.f;
            float* ho = h_out + (size_t)m * HID + n0;
            *(float4*)(ho)     = make_float4(v[0], v[1], v[2], v[3]);
            *(float4*)(ho + 4) = make_float4(v[4], v[5], v[6], v[7]);
            int c = ei[E_EDGES + m];
            float* ao = a_out + (size_t)c * HID + n0;
            red_add_v4(ao,     v[0], v[1], v[2], v[3]);
            red_add_v4(ao + 4, v[4], v[5], v[6], v[7]);
        }
    }
}

// ---------------------------------------------------------------------------
// Edge-to-node, two-phase K loop (R11):
//   phase 1: s-part (K=512, clean float4 feed), phase 2: x-part (K=133, guarded)
//   hn[n] = relu(x[n]@W[0:133] + s[n]@W[133:645] + b); pool[batch[n]] += hn
// ---------------------------------------------------------------------------
__global__ __launch_bounds__(256, 2)
void e2n_kernel(const float* __restrict__ x, const float* __restrict__ s,
                const float* __restrict__ W, const float* __restrict__ bias,
                const int* __restrict__ bat)
{
    __shared__ float As[8][132];
    __shared__ float Bs[8][128];
    const int tid = threadIdx.x;
    const int tx = tid & 15, ty = tid >> 4;
    const int bm = blockIdx.y * 128;
    const int bn = blockIdx.x * 128;

    const int arow = tid >> 1;
    const int ac4  = (tid & 1) * 4;
    const int am   = bm + arow;
    const bool aValid = (am < N_NODES);
    const float* s_src = s + (size_t)am * HID + ac4;

    const int brow = tid >> 5;
    const int bc4  = (tid & 31) * 4;

    float acc[8][8];
    #pragma unroll
    for (int i = 0; i < 8; i++)
        #pragma unroll
        for (int j = 0; j < 8; j++) acc[i][j] = 0.f;

    // ---- Phase 1: s-part, W rows FN..FN+511, clean vectorized ----
    for (int k0 = 0; k0 < HID; k0 += 8) {
        float4 av = make_float4(0.f, 0.f, 0.f, 0.f);
        if (aValid) av = *(const float4*)(s_src + k0);
        As[ac4 + 0][arow] = av.x;
        As[ac4 + 1][arow] = av.y;
        As[ac4 + 2][arow] = av.z;
        As[ac4 + 3][arow] = av.w;
        *(float4*)&Bs[brow][bc4] =
            *(const float4*)(W + (size_t)(FN + k0 + brow) * HID + bn + bc4);
        __syncthreads();

        #pragma unroll
        for (int kk = 0; kk < 8; kk++) {
            float ar[8], br[8];
            #pragma unroll
            for (int i = 0; i < 8; i++) ar[i] = As[kk][ty * 8 + i];
            #pragma unroll
            for (int j = 0; j < 8; j++) br[j] = Bs[kk][tx * 8 + j];
            #pragma unroll
            for (int i = 0; i < 8; i++)
                #pragma unroll
                for (int j = 0; j < 8; j++) acc[i][j] += ar[i] * br[j];
        }
        __syncthreads();
    }

    // ---- Phase 2: x-part, W rows 0..132, guarded (pad to 136) ----
    for (int k0 = 0; k0 < 136; k0 += 8) {
        #pragma unroll
        for (int i = 0; i < 4; i++) {
            int k = k0 + ac4 + i;
            float v = 0.f;
            if (aValid && k < FN) v = x[(size_t)am * FN + k];
            As[ac4 + i][arow] = v;
        }
        int kRow = k0 + brow;
        float4 bv = make_float4(0.f, 0.f, 0.f, 0.f);
        if (kRow < FN) bv = *(const float4*)(W + (size_t)kRow * HID + bn + bc4);
        *(float4*)&Bs[brow][bc4] = bv;
        __syncthreads();

        #pragma unroll
        for (int kk = 0; kk < 8; kk++) {
            float ar[8], br[8];
            #pragma unroll
            for (int i = 0; i < 8; i++) ar[i] = As[kk][ty * 8 + i];
            #pragma unroll
            for (int j = 0; j < 8; j++) br[j] = Bs[kk][tx * 8 + j];
            #pragma unroll
            for (int i = 0; i < 8; i++)
                #pragma unroll
                for (int j = 0; j < 8; j++) acc[i][j] += ar[i] * br[j];
        }
        __syncthreads();
    }

    const int n0 = bn + tx * 8;
    float bres[8];
    #pragma unroll
    for (int j = 0; j < 8; j++) bres[j] = bias[n0 + j];

    #pragma unroll
    for (int i = 0; i < 8; i++) {
        int m = bm + ty * 8 + i;
        if (m < N_NODES) {
            float v[8];
            #pragma unroll
            for (int j = 0; j < 8; j++) {
                float t = acc[i][j] + bres[j];
                v[j] = t > 0.f ? t : 0.f;
            }
            int g = bat[m];
            float* po = g_pool + (size_t)g * HID + n0;
            red_add_v4(po,     v[0], v[1], v[2], v[3]);
            red_add_v4(po + 4, v[4], v[5], v[6], v[7]);
        }
    }
}

// ---------------------------------------------------------------------------
// FFN head
// ---------------------------------------------------------------------------
__global__ __launch_bounds__(256)
void ffn_kernel(const float* __restrict__ W1, const float* __restrict__ b1,
                const float* __restrict__ W2, const float* __restrict__ b2,
                float* __restrict__ out)
{
    __shared__ float P[8][512];
    __shared__ float R[8 * 256];
    const int tid = threadIdx.x;
    const int g0 = blockIdx.x * 8;

    for (int i = tid; i < 8 * 512; i += 256) {
        int t = i >> 9, k = i & 511;
        P[t][k] = g_pool[(size_t)(g0 + t) * HID + k];
    }
    __syncthreads();

    float partial[8];
    #pragma unroll
    for (int t = 0; t < 8; t++) partial[t] = 0.f;

    #pragma unroll
    for (int rep = 0; rep < 2; rep++) {
        const int j = tid + rep * 256;
        float acc[8];
        #pragma unroll
        for (int t = 0; t < 8; t++) acc[t] = 0.f;
        const float bb = b1[j];
        const float w2 = W2[j];
        for (int k = 0; k < 512; k++) {
            float w = W1[(size_t)k * 512 + j];
            #pragma unroll
            for (int t = 0; t < 8; t++) acc[t] += P[t][k] * w;
        }
        #pragma unroll
        for (int t = 0; t < 8; t++) {
            float h = acc[t] + bb;
            h = h > 0.f ? h : 0.f;
            partial[t] += h * w2;
        }
    }

    #pragma unroll
    for (int t = 0; t < 8; t++) R[t * 256 + tid] = partial[t];
    __syncthreads();
    for (int srd = 128; srd > 0; srd >>= 1) {
        if (tid < srd) {
            #pragma unroll
            for (int t = 0; t < 8; t++) R[t * 256 + tid] += R[t * 256 + tid + srd];
        }
        __syncthreads();
    }
    if (tid < 8) out[g0 + tid] = R[tid * 256] + b2[0];
}

// ---------------------------------------------------------------------------
// Launch
// ---------------------------------------------------------------------------
static int find_size(const int* s, int n, int want, int occ) {
    int c = 0;
    for (int i = 0; i < n; i++)
        if (s[i] == want) { if (c == occ) return i; c++; }
    return 0;
}

extern "C" void kernel_launch(void* const* d_in, const int* in_sizes, int n_in,
                              void* d_out, int out_size)
{
    const int ix    = find_size(in_sizes, n_in, 3325000, 0);
    const int iei   = find_size(in_sizes, n_in, 200000, 0);
    const int iea   = find_size(in_sizes, n_in, 1400000, 0);
    const int ibat  = find_size(in_sizes, n_in, 25000, 0);
    const int iWei  = find_size(in_sizes, n_in, 75264, 0);
    const int iWcv  = find_size(in_sizes, n_in, 1048576, 0);
    const int ibcv  = find_size(in_sizes, n_in, 2048, 0);
    const int iWe2n = find_size(in_sizes, n_in, 330240, 0);
    const int iWf1  = find_size(in_sizes, n_in, 262144, 0);
    const int ibf2  = find_size(in_sizes, n_in, 1, 0);
    int o512[4];
    for (int k = 0; k < 4; k++) o512[k] = find_size(in_sizes, n_in, 512, k);
    int ibei, ibe2n, ibf1, iWf2;
    if (in_sizes[0] == 3325000) {
        ibei = o512[0]; ibe2n = o512[1]; ibf1 = o512[2]; iWf2 = o512[3];
    } else if (in_sizes[0] == 1048576) {
        iWf2 = o512[0]; ibe2n = o512[1]; ibei = o512[2]; ibf1 = o512[3];
    } else if (in_sizes[0] == 2048) {
        ibe2n = o512[0]; ibei = o512[1]; ibf1 = o512[2]; iWf2 = o512[3];
    } else {
        ibei = o512[0]; ibe2n = o512[1]; ibf1 = o512[2]; iWf2 = o512[3];
    }

    const float* x     = (const float*)d_in[ix];
    const int*   ei    = (const int*)d_in[iei];
    const float* ea    = (const float*)d_in[iea];
    const int*   bat   = (const int*)d_in[ibat];
    const float* W_ei  = (const float*)d_in[iWei];
    const float* b_ei  = (const float*)d_in[ibei];
    const float* W_cv  = (const float*)d_in[iWcv];
    const float* b_cv  = (const float*)d_in[ibcv];
    const float* W_e2n = (const float*)d_in[iWe2n];
    const float* b_e2n = (const float*)d_in[ibe2n];
    const float* W_f1  = (const float*)d_in[iWf1];
    const float* b_f1  = (const float*)d_in[ibf1];
    const float* W_f2  = (const float*)d_in[iWf2];
    const float* b_f2  = (const float*)d_in[ibf2];
    float* out = (float*)d_out;

    float *h0, *hA, *hB, *aA, *aB, *pool;
    cudaGetSymbolAddress((void**)&h0,   g_h0);
    cudaGetSymbolAddress((void**)&hA,   g_hA);
    cudaGetSymbolAddress((void**)&hB,   g_hB);
    cudaGetSymbolAddress((void**)&aA,   g_aA);
    cudaGetSymbolAddress((void**)&aB,   g_aB);
    cudaGetSymbolAddress((void**)&pool, g_pool);

    const size_t a_bytes = (size_t)N_NODES * HID * sizeof(float);
    const size_t p_bytes = (size_t)NG * HID * sizeof(float);
    dim3 gE(HID / 128, (E_EDGES + 127) / 128);   // (4, 782)
    dim3 gN(HID / 128, (N_NODES + 127) / 128);   // (4, 196)

    cudaMemsetAsync(aA, 0, a_bytes);
    cudaMemsetAsync(pool, 0, p_bytes);

    // Edge init, factored: X' = x@W1 + b (node-level), then combine per edge
    xproj_kernel<<<gN, 256>>>(x, W_ei, b_ei, hB);
    edge_combine_kernel<<<E_EDGES / 8, 256>>>(hB, ea, W_ei + (size_t)FN * HID, ei);

    // layer 0: h0 -> hA ; aA -> aB
    cudaMemsetAsync(aB, 0, a_bytes);
    conv_kernel<<<gE, 256>>>(h0, aA, hA, aB, W_cv + 0 * HID * HID, b_cv + 0 * HID, ei);
    // layer 1: hA -> hB ; aB -> aA
    cudaMemsetAsync(aA, 0, a_bytes);
    conv_kernel<<<gE, 256>>>(hA, aB, hB, aA, W_cv + 1 * HID * HID, b_cv + 1 * HID, ei);
    // layer 2: hB -> hA ; aA -> aB
    cudaMemsetAsync(aB, 0, a_bytes);
    conv_kernel<<<gE, 256>>>(hB, aA, hA, aB, W_cv + 2 * HID * HID, b_cv + 2 * HID, ei);
    // layer 3: hA -> hB ; aB -> aA   (aA ends as s)
    cudaMemsetAsync(aA, 0, a_bytes);
    conv_kernel<<<gE, 256>>>(hA, aB, hB, aA, W_cv + 3 * HID * HID, b_cv + 3 * HID, ei);

    e2n_kernel<<<gN, 256>>>(x, aA, W_e2n, b_e2n, bat);
    ffn_kernel<<<NG / 8, 256>>>(W_f1, b_f1, W_f2, b_f2, out);

    (void)out_size;
}

// round 13
// speedup vs baseline: 1.0047x; 1.0047x over previous
#include <cuda_runtime.h>
#include <cstdint>
#include <cstddef>

// Problem constants
#define E_EDGES 100000
#define N_NODES 25000
#define HID 512
#define NG 2048
#define FN 133
#define FE 14
#define KE2N 645

// ---------------------------------------------------------------------------
// Scratch (device globals)
// ---------------------------------------------------------------------------
__device__ float g_h0[(size_t)E_EDGES * HID];
__device__ float g_hA[(size_t)E_EDGES * HID];
__device__ float g_hB[(size_t)E_EDGES * HID];   // first 25k rows reused as X' in edge phase
__device__ float g_aA[(size_t)N_NODES * HID];
__device__ float g_aB[(size_t)N_NODES * HID];
__device__ float g_pool[(size_t)NG * HID];

// ---------------------------------------------------------------------------
// Helpers
// ---------------------------------------------------------------------------
__device__ __forceinline__ void red_add_v4(float* addr, float x, float y, float z, float w) {
    asm volatile("red.global.add.v4.f32 [%0], {%1,%2,%3,%4};"
                 :: "l"(addr), "f"(x), "f"(y), "f"(z), "f"(w) : "memory");
}

// ---------------------------------------------------------------------------
// Zero fill
// ---------------------------------------------------------------------------
__global__ void zero_kernel(float4* __restrict__ p, int n4) {
    int i = blockIdx.x * blockDim.x + threadIdx.x;
    int stride = gridDim.x * blockDim.x;
    for (; i < n4; i += stride) p[i] = make_float4(0.f, 0.f, 0.f, 0.f);
}

// ---------------------------------------------------------------------------
// Node projection: X'[n] = x[n] @ W1 + b   (M=25000, K=133 pad 136, N=512)
// ---------------------------------------------------------------------------
__global__ __launch_bounds__(256, 2)
void xproj_kernel(const float* __restrict__ x, const float* __restrict__ W,
                  const float* __restrict__ bias, float* __restrict__ Xp)
{
    __shared__ float As[8][132];
    __shared__ float Bs[8][128];
    const int tid = threadIdx.x;
    const int tx = tid & 15, ty = tid >> 4;
    const int bm = blockIdx.y * 128;
    const int bn = blockIdx.x * 128;

    const int arow = tid >> 1;
    const int ac4  = (tid & 1) * 4;
    const int am   = bm + arow;
    const bool aValid = (am < N_NODES);

    const int brow = tid >> 5;
    const int bc4  = (tid & 31) * 4;

    float acc[8][8];
    #pragma unroll
    for (int i = 0; i < 8; i++)
        #pragma unroll
        for (int j = 0; j < 8; j++) acc[i][j] = 0.f;

    for (int k0 = 0; k0 < 136; k0 += 8) {
        #pragma unroll
        for (int i = 0; i < 4; i++) {
            int k = k0 + ac4 + i;
            float v = 0.f;
            if (aValid && k < FN) v = x[(size_t)am * FN + k];
            As[ac4 + i][arow] = v;
        }
        int kRow = k0 + brow;
        float4 bv = make_float4(0.f, 0.f, 0.f, 0.f);
        if (kRow < FN) bv = *(const float4*)(W + (size_t)kRow * HID + bn + bc4);
        *(float4*)&Bs[brow][bc4] = bv;
        __syncthreads();

        #pragma unroll
        for (int kk = 0; kk < 8; kk++) {
            float ar[8], br[8];
            #pragma unroll
            for (int i = 0; i < 8; i++) ar[i] = As[kk][ty * 8 + i];
            #pragma unroll
            for (int j = 0; j < 8; j++) br[j] = Bs[kk][tx * 8 + j];
            #pragma unroll
            for (int i = 0; i < 8; i++)
                #pragma unroll
                for (int j = 0; j < 8; j++) acc[i][j] += ar[i] * br[j];
        }
        __syncthreads();
    }

    const int n0 = bn + tx * 8;
    float bres[8];
    #pragma unroll
    for (int j = 0; j < 8; j++) bres[j] = bias[n0 + j];

    #pragma unroll
    for (int i = 0; i < 8; i++) {
        int m = bm + ty * 8 + i;
        if (m < N_NODES) {
            float* xo = Xp + (size_t)m * HID + n0;
            *(float4*)(xo)     = make_float4(acc[i][0] + bres[0], acc[i][1] + bres[1],
                                             acc[i][2] + bres[2], acc[i][3] + bres[3]);
            *(float4*)(xo + 4) = make_float4(acc[i][4] + bres[4], acc[i][5] + bres[5],
                                             acc[i][6] + bres[6], acc[i][7] + bres[7]);
        }
    }
}

// ---------------------------------------------------------------------------
// Edge combine: h0[e] = relu(X'[row[e]] + ea[e] @ W2);  aA[col[e]] += h0[e]
// ---------------------------------------------------------------------------
__global__ __launch_bounds__(256)
void edge_combine_kernel(const float* __restrict__ Xp, const float* __restrict__ ea,
                         const float* __restrict__ W2, const int* __restrict__ ei)
{
    __shared__ float W2s[FE * HID];   // 28 KB
    const int tid = threadIdx.x;
    for (int i = tid; i < FE * HID; i += 256) W2s[i] = W2[i];
    __syncthreads();

    const int w = tid >> 5;
    const int lane = tid & 31;
    const int e = blockIdx.x * 8 + w;

    const int r = ei[e];
    const int c = ei[E_EDGES + e];
    float ear[FE];
    #pragma unroll
    for (int k = 0; k < FE; k++) ear[k] = ea[(size_t)e * FE + k];

    const float* xp = Xp + (size_t)r * HID;
    float* h0p = g_h0 + (size_t)e * HID;
    float* aop = g_aA + (size_t)c * HID;

    #pragma unroll
    for (int i = 0; i < 4; i++) {
        const int c4 = i * 128 + lane * 4;
        float4 acc = *(const float4*)(xp + c4);
        #pragma unroll
        for (int k = 0; k < FE; k++) {
            float4 w4 = *(const float4*)(W2s + k * HID + c4);
            acc.x += ear[k] * w4.x;  acc.y += ear[k] * w4.y;
            acc.z += ear[k] * w4.z;  acc.w += ear[k] * w4.w;
        }
        acc.x = acc.x > 0.f ? acc.x : 0.f;
        acc.y = acc.y > 0.f ? acc.y : 0.f;
        acc.z = acc.z > 0.f ? acc.z : 0.f;
        acc.w = acc.w > 0.f ? acc.w : 0.f;
        *(float4*)(h0p + c4) = acc;
        red_add_v4(aop + c4, acc.x, acc.y, acc.z, acc.w);
    }
}

// ---------------------------------------------------------------------------
// Conv layer (R10 tiling + register prefetch software pipeline):
//   h_out[e] = relu((a[row[e]] - h[e^1]) @ W + b + h0[e]); a_out[col[e]] += h_out
// ---------------------------------------------------------------------------
__global__ __launch_bounds__(256, 2)
void conv_kernel(const float* __restrict__ h_in, const float* __restrict__ a_in,
                 float* __restrict__ h_out, float* __restrict__ a_out,
                 const float* __restrict__ W, const float* __restrict__ bias,
                 const int* __restrict__ ei)
{
    __shared__ float As[8][132];
    __shared__ float Bs[8][128];
    const int tid = threadIdx.x;
    const int tx = tid & 15, ty = tid >> 4;
    const int bm = blockIdx.y * 128;
    const int bn = blockIdx.x * 128;

    const int arow = tid >> 1;
    const int ac4  = (tid & 1) * 4;
    const int am   = bm + arow;
    const bool aValid = (am < E_EDGES);
    const int r = aValid ? ei[am] : 0;
    const float* a_src = a_in + (size_t)r * HID + ac4;
    const float* h_src = h_in + (size_t)(am ^ 1) * HID + ac4;

    const int brow = tid >> 5;
    const int bc4  = (tid & 31) * 4;
    const float* w_src = W + (size_t)brow * HID + bn + bc4;

    float acc[8][8];
    #pragma unroll
    for (int i = 0; i < 8; i++)
        #pragma unroll
        for (int j = 0; j < 8; j++) acc[i][j] = 0.f;

    // Prologue: load chunk 0 into registers
    float4 aa = make_float4(0.f, 0.f, 0.f, 0.f);
    float4 hh = make_float4(0.f, 0.f, 0.f, 0.f);
    if (aValid) { aa = *(const float4*)(a_src); hh = *(const float4*)(h_src); }
    float4 bb = *(const float4*)(w_src);

    for (int k0 = 0; k0 < HID; k0 += 8) {
        As[ac4 + 0][arow] = aa.x - hh.x;
        As[ac4 + 1][arow] = aa.y - hh.y;
        As[ac4 + 2][arow] = aa.z - hh.z;
        As[ac4 + 3][arow] = aa.w - hh.w;
        *(float4*)&Bs[brow][bc4] = bb;
        __syncthreads();

        // Prefetch next chunk while this chunk computes
        if (k0 + 8 < HID) {
            if (aValid) {
                aa = *(const float4*)(a_src + k0 + 8);
                hh = *(const float4*)(h_src + k0 + 8);
            }
            bb = *(const float4*)(w_src + (size_t)(k0 + 8) * HID);
        }

        #pragma unroll
        for (int kk = 0; kk < 8; kk++) {
            float ar[8], br[8];
            #pragma unroll
            for (int i = 0; i < 8; i++) ar[i] = As[kk][ty * 8 + i];
            #pragma unroll
            for (int j = 0; j < 8; j++) br[j] = Bs[kk][tx * 8 + j];
            #pragma unroll
            for (int i = 0; i < 8; i++)
                #pragma unroll
                for (int j = 0; j < 8; j++) acc[i][j] += ar[i] * br[j];
        }
        __syncthreads();
    }

    const int n0 = bn + tx * 8;
    float bres[8];
    #pragma unroll
    for (int j = 0; j < 8; j++) bres[j] = bias[n0 + j];

    #pragma unroll
    for (int i = 0; i < 8; i++) {
        int m = bm + ty * 8 + i;
        if (m < E_EDGES) {
            const float* h0r = g_h0 + (size_t)m * HID + n0;
            float4 r0 = *(const float4*)(h0r);
            float4 r1 = *(const float4*)(h0r + 4);
            float v[8];
            v[0] = acc[i][0] + bres[0] + r0.x; v[1] = acc[i][1] + bres[1] + r0.y;
            v[2] = acc[i][2] + bres[2] + r0.z; v[3] = acc[i][3] + bres[3] + r0.w;
            v[4] = acc[i][4] + bres[4] + r1.x; v[5] = acc[i][5] + bres[5] + r1.y;
            v[6] = acc[i][6] + bres[6] + r1.z; v[7] = acc[i][7] + bres[7] + r1.w;
            #pragma unroll
            for (int j = 0; j < 8; j++) v[j] = v[j] > 0.f ? v[j] : 0.f;
            float* ho = h_out + (size_t)m * HID + n0;
            *(float4*)(ho)     = make_float4(v[0], v[1], v[2], v[3]);
            *(float4*)(ho + 4) = make_float4(v[4], v[5], v[6], v[7]);
            int c = ei[E_EDGES + m];
            float* ao = a_out + (size_t)c * HID + n0;
            red_add_v4(ao,     v[0], v[1], v[2], v[3]);
            red_add_v4(ao + 4, v[4], v[5], v[6], v[7]);
        }
    }
}

// ---------------------------------------------------------------------------
// Edge-to-node (R10 one-phase): hn[n]=relu([x[n],s[n]]@W_e2n+b); pool[batch]+=hn
// ---------------------------------------------------------------------------
__global__ __launch_bounds__(256, 2)
void e2n_kernel(const float* __restrict__ x, const float* __restrict__ s,
                const float* __restrict__ W, const float* __restrict__ bias,
                const int* __restrict__ bat)
{
    __shared__ float As[8][132];
    __shared__ float Bs[8][128];
    const int tid = threadIdx.x;
    const int tx = tid & 15, ty = tid >> 4;
    const int bm = blockIdx.y * 128;
    const int bn = blockIdx.x * 128;

    const int arow = tid >> 1;
    const int ac4  = (tid & 1) * 4;
    const int am   = bm + arow;
    const bool aValid = (am < N_NODES);

    const int brow = tid >> 5;
    const int bc4  = (tid & 31) * 4;

    float acc[8][8];
    #pragma unroll
    for (int i = 0; i < 8; i++)
        #pragma unroll
        for (int j = 0; j < 8; j++) acc[i][j] = 0.f;

    for (int k0 = 0; k0 < 648; k0 += 8) {
        #pragma unroll
        for (int i = 0; i < 4; i++) {
            int k = k0 + ac4 + i;
            float v = 0.f;
            if (aValid && k < KE2N) {
                v = (k < FN) ? x[(size_t)am * FN + k]
                             : s[(size_t)am * HID + (k - FN)];
            }
            As[ac4 + i][arow] = v;
        }
        int kRow = k0 + brow;
        float4 bv = make_float4(0.f, 0.f, 0.f, 0.f);
        if (kRow < KE2N) bv = *(const float4*)(W + (size_t)kRow * HID + bn + bc4);
        *(float4*)&Bs[brow][bc4] = bv;
        __syncthreads();

        #pragma unroll
        for (int kk = 0; kk < 8; kk++) {
            float ar[8], br[8];
            #pragma unroll
            for (int i = 0; i < 8; i++) ar[i] = As[kk][ty * 8 + i];
            #pragma unroll
            for (int j = 0; j < 8; j++) br[j] = Bs[kk][tx * 8 + j];
            #pragma unroll
            for (int i = 0; i < 8; i++)
                #pragma unroll
                for (int j = 0; j < 8; j++) acc[i][j] += ar[i] * br[j];
        }
        __syncthreads();
    }

    const int n0 = bn + tx * 8;
    float bres[8];
    #pragma unroll
    for (int j = 0; j < 8; j++) bres[j] = bias[n0 + j];

    #pragma unroll
    for (int i = 0; i < 8; i++) {
        int m = bm + ty * 8 + i;
        if (m < N_NODES) {
            float v[8];
            #pragma unroll
            for (int j = 0; j < 8; j++) {
                float t = acc[i][j] + bres[j];
                v[j] = t > 0.f ? t : 0.f;
            }
            int g = bat[m];
            float* po = g_pool + (size_t)g * HID + n0;
            red_add_v4(po,     v[0], v[1], v[2], v[3]);
            red_add_v4(po + 4, v[4], v[5], v[6], v[7]);
        }
    }
}

// ---------------------------------------------------------------------------
// FFN head
// ---------------------------------------------------------------------------
__global__ __launch_bounds__(256)
void ffn_kernel(const float* __restrict__ W1, const float* __restrict__ b1,
                const float* __restrict__ W2, const float* __restrict__ b2,
                float* __restrict__ out)
{
    __shared__ float P[8][512];
    __shared__ float R[8 * 256];
    const int tid = threadIdx.x;
    const int g0 = blockIdx.x * 8;

    for (int i = tid; i < 8 * 512; i += 256) {
        int t = i >> 9, k = i & 511;
        P[t][k] = g_pool[(size_t)(g0 + t) * HID + k];
    }
    __syncthreads();

    float partial[8];
    #pragma unroll
    for (int t = 0; t < 8; t++) partial[t] = 0.f;

    #pragma unroll
    for (int rep = 0; rep < 2; rep++) {
        const int j = tid + rep * 256;
        float acc[8];
        #pragma unroll
        for (int t = 0; t < 8; t++) acc[t] = 0.f;
        const float bb = b1[j];
        const float w2 = W2[j];
        for (int k = 0; k < 512; k++) {
            float w = W1[(size_t)k * 512 + j];
            #pragma unroll
            for (int t = 0; t < 8; t++) acc[t] += P[t][k] * w;
        }
        #pragma unroll
        for (int t = 0; t < 8; t++) {
            float h = acc[t] + bb;
            h = h > 0.f ? h : 0.f;
            partial[t] += h * w2;
        }
    }

    #pragma unroll
    for (int t = 0; t < 8; t++) R[t * 256 + tid] = partial[t];
    __syncthreads();
    for (int srd = 128; srd > 0; srd >>= 1) {
        if (tid < srd) {
            #pragma unroll
            for (int t = 0; t < 8; t++) R[t * 256 + tid] += R[t * 256 + tid + srd];
        }
        __syncthreads();
    }
    if (tid < 8) out[g0 + tid] = R[tid * 256] + b2[0];
}

// ---------------------------------------------------------------------------
// Launch
// ---------------------------------------------------------------------------
static int find_size(const int* s, int n, int want, int occ) {
    int c = 0;
    for (int i = 0; i < n; i++)
        if (s[i] == want) { if (c == occ) return i; c++; }
    return 0;
}

extern "C" void kernel_launch(void* const* d_in, const int* in_sizes, int n_in,
                              void* d_out, int out_size)
{
    const int ix    = find_size(in_sizes, n_in, 3325000, 0);
    const int iei   = find_size(in_sizes, n_in, 200000, 0);
    const int iea   = find_size(in_sizes, n_in, 1400000, 0);
    const int ibat  = find_size(in_sizes, n_in, 25000, 0);
    const int iWei  = find_size(in_sizes, n_in, 75264, 0);
    const int iWcv  = find_size(in_sizes, n_in, 1048576, 0);
    const int ibcv  = find_size(in_sizes, n_in, 2048, 0);
    const int iWe2n = find_size(in_sizes, n_in, 330240, 0);
    const int iWf1  = find_size(in_sizes, n_in, 262144, 0);
    const int ibf2  = find_size(in_sizes, n_in, 1, 0);
    int o512[4];
    for (int k = 0; k < 4; k++) o512[k] = find_size(in_sizes, n_in, 512, k);
    int ibei, ibe2n, ibf1, iWf2;
    if (in_sizes[0] == 3325000) {
        ibei = o512[0]; ibe2n = o512[1]; ibf1 = o512[2]; iWf2 = o512[3];
    } else if (in_sizes[0] == 1048576) {
        iWf2 = o512[0]; ibe2n = o512[1]; ibei = o512[2]; ibf1 = o512[3];
    } else if (in_sizes[0] == 2048) {
        ibe2n = o512[0]; ibei = o512[1]; ibf1 = o512[2]; iWf2 = o512[3];
    } else {
        ibei = o512[0]; ibe2n = o512[1]; ibf1 = o512[2]; iWf2 = o512[3];
    }

    const float* x     = (const float*)d_in[ix];
    const int*   ei    = (const int*)d_in[iei];
    const float* ea    = (const float*)d_in[iea];
    const int*   bat   = (const int*)d_in[ibat];
    const float* W_ei  = (const float*)d_in[iWei];
    const float* b_ei  = (const float*)d_in[ibei];
    const float* W_cv  = (const float*)d_in[iWcv];
    const float* b_cv  = (const float*)d_in[ibcv];
    const float* W_e2n = (const float*)d_in[iWe2n];
    const float* b_e2n = (const float*)d_in[ibe2n];
    const float* W_f1  = (const float*)d_in[iWf1];
    const float* b_f1  = (const float*)d_in[ibf1];
    const float* W_f2  = (const float*)d_in[iWf2];
    const float* b_f2  = (const float*)d_in[ibf2];
    float* out = (float*)d_out;

    float *h0, *hA, *hB, *aA, *aB, *pool;
    cudaGetSymbolAddress((void**)&h0,   g_h0);
    cudaGetSymbolAddress((void**)&hA,   g_hA);
    cudaGetSymbolAddress((void**)&hB,   g_hB);
    cudaGetSymbolAddress((void**)&aA,   g_aA);
    cudaGetSymbolAddress((void**)&aB,   g_aB);
    cudaGetSymbolAddress((void**)&pool, g_pool);

    const int a_n4 = (N_NODES * HID) / 4;
    const int p_n4 = (NG * HID) / 4;
    dim3 gE(HID / 128, (E_EDGES + 127) / 128);   // (4, 782)
    dim3 gN(HID / 128, (N_NODES + 127) / 128);   // (4, 196)

    // aA, pool, and aB (layer-0 target) zeroed up front — aB off critical path
    zero_kernel<<<(a_n4 + 255) / 256, 256>>>((float4*)aA, a_n4);
    zero_kernel<<<(p_n4 + 255) / 256, 256>>>((float4*)pool, p_n4);
    zero_kernel<<<(a_n4 + 255) / 256, 256>>>((float4*)aB, a_n4);

    // Edge init, factored: X' = x@W1 + b (node-level), then combine per edge
    xproj_kernel<<<gN, 256>>>(x, W_ei, b_ei, hB);
    edge_combine_kernel<<<E_EDGES / 8, 256>>>(hB, ea, W_ei + (size_t)FN * HID, ei);

    // layer 0: h0 -> hA ; aA -> aB
    conv_kernel<<<gE, 256>>>(h0, aA, hA, aB, W_cv + 0 * HID * HID, b_cv + 0 * HID, ei);
    // layer 1: hA -> hB ; aB -> aA
    zero_kernel<<<(a_n4 + 255) / 256, 256>>>((float4*)aA, a_n4);
    conv_kernel<<<gE, 256>>>(hA, aB, hB, aA, W_cv + 1 * HID * HID, b_cv + 1 * HID, ei);
    // layer 2: hB -> hA ; aA -> aB
    zero_kernel<<<(a_n4 + 255) / 256, 256>>>((float4*)aB, a_n4);
    conv_kernel<<<gE, 256>>>(hB, aA, hA, aB, W_cv + 2 * HID * HID, b_cv + 2 * HID, ei);
    // layer 3: hA -> hB ; aB -> aA   (aA ends as s)
    zero_kernel<<<(a_n4 + 255) / 256, 256>>>((float4*)aA, a_n4);
    conv_kernel<<<gE, 256>>>(hA, aB, hB, aA, W_cv + 3 * HID * HID, b_cv + 3 * HID, ei);

    e2n_kernel<<<gN, 256>>>(x, aA, W_e2n, b_e2n, bat);
    ffn_kernel<<<NG / 8, 256>>>(W_f1, b_f1, W_f2, b_f2, out);

    (void)out_size;
}

// round 14
// speedup vs baseline: 1.0242x; 1.0193x over previous
#include <cuda_runtime.h>
#include <cstdint>
#include <cstddef>

// Problem constants
#define E_EDGES 100000
#define N_NODES 25000
#define HID 512
#define NG 2048
#define FN 133
#define FE 14
#define KE2N 645

// ---------------------------------------------------------------------------
// Scratch (device globals)
// ---------------------------------------------------------------------------
__device__ float g_h0[(size_t)E_EDGES * HID];
__device__ float g_hA[(size_t)E_EDGES * HID];
__device__ float g_hB[(size_t)E_EDGES * HID];   // first 25k rows reused as X' in edge phase
__device__ float g_aA[(size_t)N_NODES * HID];
__device__ float g_aB[(size_t)N_NODES * HID];
__device__ float g_pool[(size_t)NG * HID];

// ---------------------------------------------------------------------------
// Helpers
// ---------------------------------------------------------------------------
__device__ __forceinline__ void red_add_v4(float* addr, float x, float y, float z, float w) {
    asm volatile("red.global.add.v4.f32 [%0], {%1,%2,%3,%4};"
                 :: "l"(addr), "f"(x), "f"(y), "f"(z), "f"(w) : "memory");
}

// ---------------------------------------------------------------------------
// Zero fill
// ---------------------------------------------------------------------------
__global__ void zero_kernel(float4* __restrict__ p, int n4) {
    int i = blockIdx.x * blockDim.x + threadIdx.x;
    int stride = gridDim.x * blockDim.x;
    for (; i < n4; i += stride) p[i] = make_float4(0.f, 0.f, 0.f, 0.f);
}

// ---------------------------------------------------------------------------
// Node projection: X'[n] = x[n] @ W1 + b   (M=25000, K=133 pad 136, N=512)
// ---------------------------------------------------------------------------
__global__ __launch_bounds__(256, 2)
void xproj_kernel(const float* __restrict__ x, const float* __restrict__ W,
                  const float* __restrict__ bias, float* __restrict__ Xp)
{
    __shared__ float As[8][132];
    __shared__ float Bs[8][128];
    const int tid = threadIdx.x;
    const int tx = tid & 15, ty = tid >> 4;
    const int bm = blockIdx.y * 128;
    const int bn = blockIdx.x * 128;

    const int arow = tid >> 1;
    const int ac4  = (tid & 1) * 4;
    const int am   = bm + arow;
    const bool aValid = (am < N_NODES);

    const int brow = tid >> 5;
    const int bc4  = (tid & 31) * 4;

    float acc[8][8];
    #pragma unroll
    for (int i = 0; i < 8; i++)
        #pragma unroll
        for (int j = 0; j < 8; j++) acc[i][j] = 0.f;

    for (int k0 = 0; k0 < 136; k0 += 8) {
        #pragma unroll
        for (int i = 0; i < 4; i++) {
            int k = k0 + ac4 + i;
            float v = 0.f;
            if (aValid && k < FN) v = x[(size_t)am * FN + k];
            As[ac4 + i][arow] = v;
        }
        int kRow = k0 + brow;
        float4 bv = make_float4(0.f, 0.f, 0.f, 0.f);
        if (kRow < FN) bv = *(const float4*)(W + (size_t)kRow * HID + bn + bc4);
        *(float4*)&Bs[brow][bc4] = bv;
        __syncthreads();

        #pragma unroll
        for (int kk = 0; kk < 8; kk++) {
            float ar[8], br[8];
            #pragma unroll
            for (int i = 0; i < 8; i++) ar[i] = As[kk][ty * 8 + i];
            #pragma unroll
            for (int j = 0; j < 8; j++) br[j] = Bs[kk][tx * 8 + j];
            #pragma unroll
            for (int i = 0; i < 8; i++)
                #pragma unroll
                for (int j = 0; j < 8; j++) acc[i][j] += ar[i] * br[j];
        }
        __syncthreads();
    }

    const int n0 = bn + tx * 8;
    float bres[8];
    #pragma unroll
    for (int j = 0; j < 8; j++) bres[j] = bias[n0 + j];

    #pragma unroll
    for (int i = 0; i < 8; i++) {
        int m = bm + ty * 8 + i;
        if (m < N_NODES) {
            float* xo = Xp + (size_t)m * HID + n0;
            *(float4*)(xo)     = make_float4(acc[i][0] + bres[0], acc[i][1] + bres[1],
                                             acc[i][2] + bres[2], acc[i][3] + bres[3]);
            *(float4*)(xo + 4) = make_float4(acc[i][4] + bres[4], acc[i][5] + bres[5],
                                             acc[i][6] + bres[6], acc[i][7] + bres[7]);
        }
    }
}

// ---------------------------------------------------------------------------
// Edge combine: h0[e] = relu(X'[row[e]] + ea[e] @ W2);  aA[col[e]] += h0[e]
// 2 warps per edge (half-row each) for doubled memory-level parallelism.
// grid = 25000 blocks, 4 edges/block.
// ---------------------------------------------------------------------------
__global__ __launch_bounds__(256)
void edge_combine_kernel(const float* __restrict__ Xp, const float* __restrict__ ea,
                         const float* __restrict__ W2, const int* __restrict__ ei)
{
    __shared__ float W2s[FE * HID];   // 28 KB
    const int tid = threadIdx.x;
    for (int i = tid; i < FE * HID; i += 256) W2s[i] = W2[i];
    __syncthreads();

    const int w = tid >> 5;
    const int lane = tid & 31;
    const int e = blockIdx.x * 4 + (w >> 1);   // 4 edges per block
    const int half = w & 1;                     // half-row per warp

    const int r = ei[e];
    const int c = ei[E_EDGES + e];
    float ear[FE];
    #pragma unroll
    for (int k = 0; k < FE; k++) ear[k] = ea[(size_t)e * FE + k];

    const float* xp = Xp + (size_t)r * HID + half * 256;
    float* h0p = g_h0 + (size_t)e * HID + half * 256;
    float* aop = g_aA + (size_t)c * HID + half * 256;

    #pragma unroll
    for (int i = 0; i < 2; i++) {
        const int c4 = i * 128 + lane * 4;
        float4 acc = *(const float4*)(xp + c4);
        const float* wbase = W2s + half * 256 + c4;
        #pragma unroll
        for (int k = 0; k < FE; k++) {
            float4 w4 = *(const float4*)(wbase + k * HID);
            acc.x += ear[k] * w4.x;  acc.y += ear[k] * w4.y;
            acc.z += ear[k] * w4.z;  acc.w += ear[k] * w4.w;
        }
        acc.x = acc.x > 0.f ? acc.x : 0.f;
        acc.y = acc.y > 0.f ? acc.y : 0.f;
        acc.z = acc.z > 0.f ? acc.z : 0.f;
        acc.w = acc.w > 0.f ? acc.w : 0.f;
        *(float4*)(h0p + c4) = acc;
        red_add_v4(aop + c4, acc.x, acc.y, acc.z, acc.w);
    }
}

// ---------------------------------------------------------------------------
// Conv layer (R10-proven, 128x128, 256 threads):
//   h_out[e] = relu((a[row[e]] - h[e^1]) @ W + b + h0[e]); a_out[col[e]] += h_out
// ---------------------------------------------------------------------------
__global__ __launch_bounds__(256, 2)
void conv_kernel(const float* __restrict__ h_in, const float* __restrict__ a_in,
                 float* __restrict__ h_out, float* __restrict__ a_out,
                 const float* __restrict__ W, const float* __restrict__ bias,
                 const int* __restrict__ ei)
{
    __shared__ float As[8][132];
    __shared__ float Bs[8][128];
    const int tid = threadIdx.x;
    const int tx = tid & 15, ty = tid >> 4;
    const int bm = blockIdx.y * 128;
    const int bn = blockIdx.x * 128;

    const int arow = tid >> 1;
    const int ac4  = (tid & 1) * 4;
    const int am   = bm + arow;
    const bool aValid = (am < E_EDGES);
    const int r = aValid ? ei[am] : 0;
    const float* a_src = a_in + (size_t)r * HID + ac4;
    const float* h_src = h_in + (size_t)(am ^ 1) * HID + ac4;

    const int brow = tid >> 5;
    const int bc4  = (tid & 31) * 4;
    const float* w_src = W + (size_t)brow * HID + bn + bc4;

    float acc[8][8];
    #pragma unroll
    for (int i = 0; i < 8; i++)
        #pragma unroll
        for (int j = 0; j < 8; j++) acc[i][j] = 0.f;

    for (int k0 = 0; k0 < HID; k0 += 8) {
        float4 av = make_float4(0.f, 0.f, 0.f, 0.f);
        if (aValid) {
            float4 aa = *(const float4*)(a_src + k0);
            float4 hh = *(const float4*)(h_src + k0);
            av.x = aa.x - hh.x; av.y = aa.y - hh.y;
            av.z = aa.z - hh.z; av.w = aa.w - hh.w;
        }
        As[ac4 + 0][arow] = av.x;
        As[ac4 + 1][arow] = av.y;
        As[ac4 + 2][arow] = av.z;
        As[ac4 + 3][arow] = av.w;
        *(float4*)&Bs[brow][bc4] = *(const float4*)(w_src + (size_t)k0 * HID);
        __syncthreads();

        #pragma unroll
        for (int kk = 0; kk < 8; kk++) {
            float ar[8], br[8];
            #pragma unroll
            for (int i = 0; i < 8; i++) ar[i] = As[kk][ty * 8 + i];
            #pragma unroll
            for (int j = 0; j < 8; j++) br[j] = Bs[kk][tx * 8 + j];
            #pragma unroll
            for (int i = 0; i < 8; i++)
                #pragma unroll
                for (int j = 0; j < 8; j++) acc[i][j] += ar[i] * br[j];
        }
        __syncthreads();
    }

    const int n0 = bn + tx * 8;
    float bres[8];
    #pragma unroll
    for (int j = 0; j < 8; j++) bres[j] = bias[n0 + j];

    #pragma unroll
    for (int i = 0; i < 8; i++) {
        int m = bm + ty * 8 + i;
        if (m < E_EDGES) {
            const float* h0r = g_h0 + (size_t)m * HID + n0;
            float4 r0 = *(const float4*)(h0r);
            float4 r1 = *(const float4*)(h0r + 4);
            float v[8];
            v[0] = acc[i][0] + bres[0] + r0.x; v[1] = acc[i][1] + bres[1] + r0.y;
            v[2] = acc[i][2] + bres[2] + r0.z; v[3] = acc[i][3] + bres[3] + r0.w;
            v[4] = acc[i][4] + bres[4] + r1.x; v[5] = acc[i][5] + bres[5] + r1.y;
            v[6] = acc[i][6] + bres[6] + r1.z; v[7] = acc[i][7] + bres[7] + r1.w;
            #pragma unroll
            for (int j = 0; j < 8; j++) v[j] = v[j] > 0.f ? v[j] : 0.f;
            float* ho = h_out + (size_t)m * HID + n0;
            *(float4*)(ho)     = make_float4(v[0], v[1], v[2], v[3]);
            *(float4*)(ho + 4) = make_float4(v[4], v[5], v[6], v[7]);
            int c = ei[E_EDGES + m];
            float* ao = a_out + (size_t)c * HID + n0;
            red_add_v4(ao,     v[0], v[1], v[2], v[3]);
            red_add_v4(ao + 4, v[4], v[5], v[6], v[7]);
        }
    }
}

// ---------------------------------------------------------------------------
// Edge-to-node (R10 one-phase): hn[n]=relu([x[n],s[n]]@W_e2n+b); pool[batch]+=hn
// ---------------------------------------------------------------------------
__global__ __launch_bounds__(256, 2)
void e2n_kernel(const float* __restrict__ x, const float* __restrict__ s,
                const float* __restrict__ W, const float* __restrict__ bias,
                const int* __restrict__ bat)
{
    __shared__ float As[8][132];
    __shared__ float Bs[8][128];
    const int tid = threadIdx.x;
    const int tx = tid & 15, ty = tid >> 4;
    const int bm = blockIdx.y * 128;
    const int bn = blockIdx.x * 128;

    const int arow = tid >> 1;
    const int ac4  = (tid & 1) * 4;
    const int am   = bm + arow;
    const bool aValid = (am < N_NODES);

    const int brow = tid >> 5;
    const int bc4  = (tid & 31) * 4;

    float acc[8][8];
    #pragma unroll
    for (int i = 0; i < 8; i++)
        #pragma unroll
        for (int j = 0; j < 8; j++) acc[i][j] = 0.f;

    for (int k0 = 0; k0 < 648; k0 += 8) {
        #pragma unroll
        for (int i = 0; i < 4; i++) {
            int k = k0 + ac4 + i;
            float v = 0.f;
            if (aValid && k < KE2N) {
                v = (k < FN) ? x[(size_t)am * FN + k]
                             : s[(size_t)am * HID + (k - FN)];
            }
            As[ac4 + i][arow] = v;
        }
        int kRow = k0 + brow;
        float4 bv = make_float4(0.f, 0.f, 0.f, 0.f);
        if (kRow < KE2N) bv = *(const float4*)(W + (size_t)kRow * HID + bn + bc4);
        *(float4*)&Bs[brow][bc4] = bv;
        __syncthreads();

        #pragma unroll
        for (int kk = 0; kk < 8; kk++) {
            float ar[8], br[8];
            #pragma unroll
            for (int i = 0; i < 8; i++) ar[i] = As[kk][ty * 8 + i];
            #pragma unroll
            for (int j = 0; j < 8; j++) br[j] = Bs[kk][tx * 8 + j];
            #pragma unroll
            for (int i = 0; i < 8; i++)
                #pragma unroll
                for (int j = 0; j < 8; j++) acc[i][j] += ar[i] * br[j];
        }
        __syncthreads();
    }

    const int n0 = bn + tx * 8;
    float bres[8];
    #pragma unroll
    for (int j = 0; j < 8; j++) bres[j] = bias[n0 + j];

    #pragma unroll
    for (int i = 0; i < 8; i++) {
        int m = bm + ty * 8 + i;
        if (m < N_NODES) {
            float v[8];
            #pragma unroll
            for (int j = 0; j < 8; j++) {
                float t = acc[i][j] + bres[j];
                v[j] = t > 0.f ? t : 0.f;
            }
            int g = bat[m];
            float* po = g_pool + (size_t)g * HID + n0;
            red_add_v4(po,     v[0], v[1], v[2], v[3]);
            red_add_v4(po + 4, v[4], v[5], v[6], v[7]);
        }
    }
}

// ---------------------------------------------------------------------------
// FFN head
// ---------------------------------------------------------------------------
__global__ __launch_bounds__(256)
void ffn_kernel(const float* __restrict__ W1, const float* __restrict__ b1,
                const float* __restrict__ W2, const float* __restrict__ b2,
                float* __restrict__ out)
{
    __shared__ float P[8][512];
    __shared__ float R[8 * 256];
    const int tid = threadIdx.x;
    const int g0 = blockIdx.x * 8;

    for (int i = tid; i < 8 * 512; i += 256) {
        int t = i >> 9, k = i & 511;
        P[t][k] = g_pool[(size_t)(g0 + t) * HID + k];
    }
    __syncthreads();

    float partial[8];
    #pragma unroll
    for (int t = 0; t < 8; t++) partial[t] = 0.f;

    #pragma unroll
    for (int rep = 0; rep < 2; rep++) {
        const int j = tid + rep * 256;
        float acc[8];
        #pragma unroll
        for (int t = 0; t < 8; t++) acc[t] = 0.f;
        const float bb = b1[j];
        const float w2 = W2[j];
        for (int k = 0; k < 512; k++) {
            float w = W1[(size_t)k * 512 + j];
            #pragma unroll
            for (int t = 0; t < 8; t++) acc[t] += P[t][k] * w;
        }
        #pragma unroll
        for (int t = 0; t < 8; t++) {
            float h = acc[t] + bb;
            h = h > 0.f ? h : 0.f;
            partial[t] += h * w2;
        }
    }

    #pragma unroll
    for (int t = 0; t < 8; t++) R[t * 256 + tid] = partial[t];
    __syncthreads();
    for (int srd = 128; srd > 0; srd >>= 1) {
        if (tid < srd) {
            #pragma unroll
            for (int t = 0; t < 8; t++) R[t * 256 + tid] += R[t * 256 + tid + srd];
        }
        __syncthreads();
    }
    if (tid < 8) out[g0 + tid] = R[tid * 256] + b2[0];
}

// ---------------------------------------------------------------------------
// Launch
// ---------------------------------------------------------------------------
static int find_size(const int* s, int n, int want, int occ) {
    int c = 0;
    for (int i = 0; i < n; i++)
        if (s[i] == want) { if (c == occ) return i; c++; }
    return 0;
}

extern "C" void kernel_launch(void* const* d_in, const int* in_sizes, int n_in,
                              void* d_out, int out_size)
{
    const int ix    = find_size(in_sizes, n_in, 3325000, 0);
    const int iei   = find_size(in_sizes, n_in, 200000, 0);
    const int iea   = find_size(in_sizes, n_in, 1400000, 0);
    const int ibat  = find_size(in_sizes, n_in, 25000, 0);
    const int iWei  = find_size(in_sizes, n_in, 75264, 0);
    const int iWcv  = find_size(in_sizes, n_in, 1048576, 0);
    const int ibcv  = find_size(in_sizes, n_in, 2048, 0);
    const int iWe2n = find_size(in_sizes, n_in, 330240, 0);
    const int iWf1  = find_size(in_sizes, n_in, 262144, 0);
    const int ibf2  = find_size(in_sizes, n_in, 1, 0);
    int o512[4];
    for (int k = 0; k < 4; k++) o512[k] = find_size(in_sizes, n_in, 512, k);
    int ibei, ibe2n, ibf1, iWf2;
    if (in_sizes[0] == 3325000) {
        ibei = o512[0]; ibe2n = o512[1]; ibf1 = o512[2]; iWf2 = o512[3];
    } else if (in_sizes[0] == 1048576) {
        iWf2 = o512[0]; ibe2n = o512[1]; ibei = o512[2]; ibf1 = o512[3];
    } else if (in_sizes[0] == 2048) {
        ibe2n = o512[0]; ibei = o512[1]; ibf1 = o512[2]; iWf2 = o512[3];
    } else {
        ibei = o512[0]; ibe2n = o512[1]; ibf1 = o512[2]; iWf2 = o512[3];
    }

    const float* x     = (const float*)d_in[ix];
    const int*   ei    = (const int*)d_in[iei];
    const float* ea    = (const float*)d_in[iea];
    const int*   bat   = (const int*)d_in[ibat];
    const float* W_ei  = (const float*)d_in[iWei];
    const float* b_ei  = (const float*)d_in[ibei];
    const float* W_cv  = (const float*)d_in[iWcv];
    const float* b_cv  = (const float*)d_in[ibcv];
    const float* W_e2n = (const float*)d_in[iWe2n];
    const float* b_e2n = (const float*)d_in[ibe2n];
    const float* W_f1  = (const float*)d_in[iWf1];
    const float* b_f1  = (const float*)d_in[ibf1];
    const float* W_f2  = (const float*)d_in[iWf2];
    const float* b_f2  = (const float*)d_in[ibf2];
    float* out = (float*)d_out;

    float *h0, *hA, *hB, *aA, *aB, *pool;
    cudaGetSymbolAddress((void**)&h0,   g_h0);
    cudaGetSymbolAddress((void**)&hA,   g_hA);
    cudaGetSymbolAddress((void**)&hB,   g_hB);
    cudaGetSymbolAddress((void**)&aA,   g_aA);
    cudaGetSymbolAddress((void**)&aB,   g_aB);
    cudaGetSymbolAddress((void**)&pool, g_pool);

    const int a_n4 = (N_NODES * HID) / 4;
    const int p_n4 = (NG * HID) / 4;
    dim3 gE(HID / 128, (E_EDGES + 127) / 128);   // (4, 782)
    dim3 gN(HID / 128, (N_NODES + 127) / 128);   // (4, 196)

    // aA, pool, and layer-0 target aB zeroed up front (aB off critical path)
    zero_kernel<<<(a_n4 + 255) / 256, 256>>>((float4*)aA, a_n4);
    zero_kernel<<<(p_n4 + 255) / 256, 256>>>((float4*)pool, p_n4);
    zero_kernel<<<(a_n4 + 255) / 256, 256>>>((float4*)aB, a_n4);

    // Edge init, factored: X' = x@W1 + b (node-level), then combine per edge
    xproj_kernel<<<gN, 256>>>(x, W_ei, b_ei, hB);
    edge_combine_kernel<<<E_EDGES / 4, 256>>>(hB, ea, W_ei + (size_t)FN * HID, ei);

    // layer 0: h0 -> hA ; aA -> aB
    conv_kernel<<<gE, 256>>>(h0, aA, hA, aB, W_cv + 0 * HID * HID, b_cv + 0 * HID, ei);
    // layer 1: hA -> hB ; aB -> aA
    zero_kernel<<<(a_n4 + 255) / 256, 256>>>((float4*)aA, a_n4);
    conv_kernel<<<gE, 256>>>(hA, aB, hB, aA, W_cv + 1 * HID * HID, b_cv + 1 * HID, ei);
    // layer 2: hB -> hA ; aA -> aB
    zero_kernel<<<(a_n4 + 255) / 256, 256>>>((float4*)aB, a_n4);
    conv_kernel<<<gE, 256>>>(hB, aA, hA, aB, W_cv + 2 * HID * HID, b_cv + 2 * HID, ei);
    // layer 3: hA -> hB ; aB -> aA   (aA ends as s)
    zero_kernel<<<(a_n4 + 255) / 256, 256>>>((float4*)aA, a_n4);
    conv_kernel<<<gE, 256>>>(hA, aB, hB, aA, W_cv + 3 * HID * HID, b_cv + 3 * HID, ei);

    e2n_kernel<<<gN, 256>>>(x, aA, W_e2n, b_e2n, bat);
    ffn_kernel<<<NG / 8, 256>>>(W_f1, b_f1, W_f2, b_f2, out);

    (void)out_size;
}

// round 15
// speedup vs baseline: 1.0306x; 1.0062x over previous
#include <cuda_runtime.h>
#include <cstdint>
#include <cstddef>

// Problem constants
#define E_EDGES 100000
#define N_NODES 25000
#define HID 512
#define NG 2048
#define FN 133
#define FE 14
#define KE2N 645

// ---------------------------------------------------------------------------
// Scratch (device globals)
// ---------------------------------------------------------------------------
__device__ float g_h0[(size_t)E_EDGES * HID];
__device__ float g_hA[(size_t)E_EDGES * HID];
__device__ float g_hB[(size_t)E_EDGES * HID];   // first 25k rows reused as X' in edge phase
__device__ float g_aA[(size_t)N_NODES * HID];
__device__ float g_aB[(size_t)N_NODES * HID];
__device__ float g_pool[(size_t)NG * HID];

// ---------------------------------------------------------------------------
// Helpers
// ---------------------------------------------------------------------------
__device__ __forceinline__ void red_add_v4(float* addr, float x, float y, float z, float w) {
    asm volatile("red.global.add.v4.f32 [%0], {%1,%2,%3,%4};"
                 :: "l"(addr), "f"(x), "f"(y), "f"(z), "f"(w) : "memory");
}

// ---------------------------------------------------------------------------
// Zero fill
// ---------------------------------------------------------------------------
__global__ void zero_kernel(float4* __restrict__ p, int n4) {
    int i = blockIdx.x * blockDim.x + threadIdx.x;
    int stride = gridDim.x * blockDim.x;
    for (; i < n4; i += stride) p[i] = make_float4(0.f, 0.f, 0.f, 0.f);
}

// ---------------------------------------------------------------------------
// Node projection: X'[n] = x[n] @ W1 + b   (M=25000, K=133 pad 136, N=512)
// ---------------------------------------------------------------------------
__global__ __launch_bounds__(256, 2)
void xproj_kernel(const float* __restrict__ x, const float* __restrict__ W,
                  const float* __restrict__ bias, float* __restrict__ Xp)
{
    __shared__ float As[8][132];
    __shared__ float Bs[8][128];
    const int tid = threadIdx.x;
    const int tx = tid & 15, ty = tid >> 4;
    const int bm = blockIdx.y * 128;
    const int bn = blockIdx.x * 128;

    const int arow = tid >> 1;
    const int ac4  = (tid & 1) * 4;
    const int am   = bm + arow;
    const bool aValid = (am < N_NODES);

    const int brow = tid >> 5;
    const int bc4  = (tid & 31) * 4;

    float acc[8][8];
    #pragma unroll
    for (int i = 0; i < 8; i++)
        #pragma unroll
        for (int j = 0; j < 8; j++) acc[i][j] = 0.f;

    for (int k0 = 0; k0 < 136; k0 += 8) {
        #pragma unroll
        for (int i = 0; i < 4; i++) {
            int k = k0 + ac4 + i;
            float v = 0.f;
            if (aValid && k < FN) v = x[(size_t)am * FN + k];
            As[ac4 + i][arow] = v;
        }
        int kRow = k0 + brow;
        float4 bv = make_float4(0.f, 0.f, 0.f, 0.f);
        if (kRow < FN) bv = *(const float4*)(W + (size_t)kRow * HID + bn + bc4);
        *(float4*)&Bs[brow][bc4] = bv;
        __syncthreads();

        #pragma unroll
        for (int kk = 0; kk < 8; kk++) {
            float ar[8], br[8];
            #pragma unroll
            for (int i = 0; i < 8; i++) ar[i] = As[kk][ty * 8 + i];
            #pragma unroll
            for (int j = 0; j < 8; j++) br[j] = Bs[kk][tx * 8 + j];
            #pragma unroll
            for (int i = 0; i < 8; i++)
                #pragma unroll
                for (int j = 0; j < 8; j++) acc[i][j] += ar[i] * br[j];
        }
        __syncthreads();
    }

    const int n0 = bn + tx * 8;
    float bres[8];
    #pragma unroll
    for (int j = 0; j < 8; j++) bres[j] = bias[n0 + j];

    #pragma unroll
    for (int i = 0; i < 8; i++) {
        int m = bm + ty * 8 + i;
        if (m < N_NODES) {
            float* xo = Xp + (size_t)m * HID + n0;
            *(float4*)(xo)     = make_float4(acc[i][0] + bres[0], acc[i][1] + bres[1],
                                             acc[i][2] + bres[2], acc[i][3] + bres[3]);
            *(float4*)(xo + 4) = make_float4(acc[i][4] + bres[4], acc[i][5] + bres[5],
                                             acc[i][6] + bres[6], acc[i][7] + bres[7]);
        }
    }
}

// ---------------------------------------------------------------------------
// Edge combine (R10-proven, one warp per edge):
//   h0[e] = relu(X'[row[e]] + ea[e] @ W2);  aA[col[e]] += h0[e]
// ---------------------------------------------------------------------------
__global__ __launch_bounds__(256)
void edge_combine_kernel(const float* __restrict__ Xp, const float* __restrict__ ea,
                         const float* __restrict__ W2, const int* __restrict__ ei)
{
    __shared__ float W2s[FE * HID];   // 28 KB
    const int tid = threadIdx.x;
    for (int i = tid; i < FE * HID; i += 256) W2s[i] = W2[i];
    __syncthreads();

    const int w = tid >> 5;
    const int lane = tid & 31;
    const int e = blockIdx.x * 8 + w;     // grid 12500 * 8 = 100000 exact

    const int r = ei[e];
    const int c = ei[E_EDGES + e];
    float ear[FE];
    #pragma unroll
    for (int k = 0; k < FE; k++) ear[k] = ea[(size_t)e * FE + k];

    const float* xp = Xp + (size_t)r * HID;
    float* h0p = g_h0 + (size_t)e * HID;
    float* aop = g_aA + (size_t)c * HID;

    #pragma unroll
    for (int i = 0; i < 4; i++) {
        const int c4 = i * 128 + lane * 4;
        float4 acc = *(const float4*)(xp + c4);
        #pragma unroll
        for (int k = 0; k < FE; k++) {
            float4 w4 = *(const float4*)(W2s + k * HID + c4);
            acc.x += ear[k] * w4.x;  acc.y += ear[k] * w4.y;
            acc.z += ear[k] * w4.z;  acc.w += ear[k] * w4.w;
        }
        acc.x = acc.x > 0.f ? acc.x : 0.f;
        acc.y = acc.y > 0.f ? acc.y : 0.f;
        acc.z = acc.z > 0.f ? acc.z : 0.f;
        acc.w = acc.w > 0.f ? acc.w : 0.f;
        *(float4*)(h0p + c4) = acc;
        red_add_v4(aop + c4, acc.x, acc.y, acc.z, acc.w);
    }
}

// ---------------------------------------------------------------------------
// Conv layer (R10-proven, 128x128, 256 threads):
//   h_out[e] = relu((a[row[e]] - h[e^1]) @ W + b + h0[e]); a_out[col[e]] += h_out
// ---------------------------------------------------------------------------
__global__ __launch_bounds__(256, 2)
void conv_kernel(const float* __restrict__ h_in, const float* __restrict__ a_in,
                 float* __restrict__ h_out, float* __restrict__ a_out,
                 const float* __restrict__ W, const float* __restrict__ bias,
                 const int* __restrict__ ei)
{
    __shared__ float As[8][132];
    __shared__ float Bs[8][128];
    const int tid = threadIdx.x;
    const int tx = tid & 15, ty = tid >> 4;
    const int bm = blockIdx.y * 128;
    const int bn = blockIdx.x * 128;

    const int arow = tid >> 1;
    const int ac4  = (tid & 1) * 4;
    const int am   = bm + arow;
    const bool aValid = (am < E_EDGES);
    const int r = aValid ? ei[am] : 0;
    const float* a_src = a_in + (size_t)r * HID + ac4;
    const float* h_src = h_in + (size_t)(am ^ 1) * HID + ac4;

    const int brow = tid >> 5;
    const int bc4  = (tid & 31) * 4;
    const float* w_src = W + (size_t)brow * HID + bn + bc4;

    float acc[8][8];
    #pragma unroll
    for (int i = 0; i < 8; i++)
        #pragma unroll
        for (int j = 0; j < 8; j++) acc[i][j] = 0.f;

    for (int k0 = 0; k0 < HID; k0 += 8) {
        float4 av = make_float4(0.f, 0.f, 0.f, 0.f);
        if (aValid) {
            float4 aa = *(const float4*)(a_src + k0);
            float4 hh = *(const float4*)(h_src + k0);
            av.x = aa.x - hh.x; av.y = aa.y - hh.y;
            av.z = aa.z - hh.z; av.w = aa.w - hh.w;
        }
        As[ac4 + 0][arow] = av.x;
        As[ac4 + 1][arow] = av.y;
        As[ac4 + 2][arow] = av.z;
        As[ac4 + 3][arow] = av.w;
        *(float4*)&Bs[brow][bc4] = *(const float4*)(w_src + (size_t)k0 * HID);
        __syncthreads();

        #pragma unroll
        for (int kk = 0; kk < 8; kk++) {
            float ar[8], br[8];
            #pragma unroll
            for (int i = 0; i < 8; i++) ar[i] = As[kk][ty * 8 + i];
            #pragma unroll
            for (int j = 0; j < 8; j++) br[j] = Bs[kk][tx * 8 + j];
            #pragma unroll
            for (int i = 0; i < 8; i++)
                #pragma unroll
                for (int j = 0; j < 8; j++) acc[i][j] += ar[i] * br[j];
        }
        __syncthreads();
    }

    const int n0 = bn + tx * 8;
    float bres[8];
    #pragma unroll
    for (int j = 0; j < 8; j++) bres[j] = bias[n0 + j];

    #pragma unroll
    for (int i = 0; i < 8; i++) {
        int m = bm + ty * 8 + i;
        if (m < E_EDGES) {
            const float* h0r = g_h0 + (size_t)m * HID + n0;
            float4 r0 = *(const float4*)(h0r);
            float4 r1 = *(const float4*)(h0r + 4);
            float v[8];
            v[0] = acc[i][0] + bres[0] + r0.x; v[1] = acc[i][1] + bres[1] + r0.y;
            v[2] = acc[i][2] + bres[2] + r0.z; v[3] = acc[i][3] + bres[3] + r0.w;
            v[4] = acc[i][4] + bres[4] + r1.x; v[5] = acc[i][5] + bres[5] + r1.y;
            v[6] = acc[i][6] + bres[6] + r1.z; v[7] = acc[i][7] + bres[7] + r1.w;
            #pragma unroll
            for (int j = 0; j < 8; j++) v[j] = v[j] > 0.f ? v[j] : 0.f;
            float* ho = h_out + (size_t)m * HID + n0;
            *(float4*)(ho)     = make_float4(v[0], v[1], v[2], v[3]);
            *(float4*)(ho + 4) = make_float4(v[4], v[5], v[6], v[7]);
            int c = ei[E_EDGES + m];
            float* ao = a_out + (size_t)c * HID + n0;
            red_add_v4(ao,     v[0], v[1], v[2], v[3]);
            red_add_v4(ao + 4, v[4], v[5], v[6], v[7]);
        }
    }
}

// ---------------------------------------------------------------------------
// Edge-to-node (R10-proven): hn[n]=relu([x[n],s[n]]@W_e2n+b); pool[batch]+=hn
// ---------------------------------------------------------------------------
__global__ __launch_bounds__(256, 2)
void e2n_kernel(const float* __restrict__ x, const float* __restrict__ s,
                const float* __restrict__ W, const float* __restrict__ bias,
                const int* __restrict__ bat)
{
    __shared__ float As[8][132];
    __shared__ float Bs[8][128];
    const int tid = threadIdx.x;
    const int tx = tid & 15, ty = tid >> 4;
    const int bm = blockIdx.y * 128;
    const int bn = blockIdx.x * 128;

    const int arow = tid >> 1;
    const int ac4  = (tid & 1) * 4;
    const int am   = bm + arow;
    const bool aValid = (am < N_NODES);

    const int brow = tid >> 5;
    const int bc4  = (tid & 31) * 4;

    float acc[8][8];
    #pragma unroll
    for (int i = 0; i < 8; i++)
        #pragma unroll
        for (int j = 0; j < 8; j++) acc[i][j] = 0.f;

    for (int k0 = 0; k0 < 648; k0 += 8) {
        #pragma unroll
        for (int i = 0; i < 4; i++) {
            int k = k0 + ac4 + i;
            float v = 0.f;
            if (aValid && k < KE2N) {
                v = (k < FN) ? x[(size_t)am * FN + k]
                             : s[(size_t)am * HID + (k - FN)];
            }
            As[ac4 + i][arow] = v;
        }
        int kRow = k0 + brow;
        float4 bv = make_float4(0.f, 0.f, 0.f, 0.f);
        if (kRow < KE2N) bv = *(const float4*)(W + (size_t)kRow * HID + bn + bc4);
        *(float4*)&Bs[brow][bc4] = bv;
        __syncthreads();

        #pragma unroll
        for (int kk = 0; kk < 8; kk++) {
            float ar[8], br[8];
            #pragma unroll
            for (int i = 0; i < 8; i++) ar[i] = As[kk][ty * 8 + i];
            #pragma unroll
            for (int j = 0; j < 8; j++) br[j] = Bs[kk][tx * 8 + j];
            #pragma unroll
            for (int i = 0; i < 8; i++)
                #pragma unroll
                for (int j = 0; j < 8; j++) acc[i][j] += ar[i] * br[j];
        }
        __syncthreads();
    }

    const int n0 = bn + tx * 8;
    float bres[8];
    #pragma unroll
    for (int j = 0; j < 8; j++) bres[j] = bias[n0 + j];

    #pragma unroll
    for (int i = 0; i < 8; i++) {
        int m = bm + ty * 8 + i;
        if (m < N_NODES) {
            float v[8];
            #pragma unroll
            for (int j = 0; j < 8; j++) {
                float t = acc[i][j] + bres[j];
                v[j] = t > 0.f ? t : 0.f;
            }
            int g = bat[m];
            float* po = g_pool + (size_t)g * HID + n0;
            red_add_v4(po,     v[0], v[1], v[2], v[3]);
            red_add_v4(po + 4, v[4], v[5], v[6], v[7]);
        }
    }
}

// ---------------------------------------------------------------------------
// FFN head
// ---------------------------------------------------------------------------
__global__ __launch_bounds__(256)
void ffn_kernel(const float* __restrict__ W1, const float* __restrict__ b1,
                const float* __restrict__ W2, const float* __restrict__ b2,
                float* __restrict__ out)
{
    __shared__ float P[8][512];
    __shared__ float R[8 * 256];
    const int tid = threadIdx.x;
    const int g0 = blockIdx.x * 8;

    for (int i = tid; i < 8 * 512; i += 256) {
        int t = i >> 9, k = i & 511;
        P[t][k] = g_pool[(size_t)(g0 + t) * HID + k];
    }
    __syncthreads();

    float partial[8];
    #pragma unroll
    for (int t = 0; t < 8; t++) partial[t] = 0.f;

    #pragma unroll
    for (int rep = 0; rep < 2; rep++) {
        const int j = tid + rep * 256;
        float acc[8];
        #pragma unroll
        for (int t = 0; t < 8; t++) acc[t] = 0.f;
        const float bb = b1[j];
        const float w2 = W2[j];
        for (int k = 0; k < 512; k++) {
            float w = W1[(size_t)k * 512 + j];
            #pragma unroll
            for (int t = 0; t < 8; t++) acc[t] += P[t][k] * w;
        }
        #pragma unroll
        for (int t = 0; t < 8; t++) {
            float h = acc[t] + bb;
            h = h > 0.f ? h : 0.f;
            partial[t] += h * w2;
        }
    }

    #pragma unroll
    for (int t = 0; t < 8; t++) R[t * 256 + tid] = partial[t];
    __syncthreads();
    for (int srd = 128; srd > 0; srd >>= 1) {
        if (tid < srd) {
            #pragma unroll
            for (int t = 0; t < 8; t++) R[t * 256 + tid] += R[t * 256 + tid + srd];
        }
        __syncthreads();
    }
    if (tid < 8) out[g0 + tid] = R[tid * 256] + b2[0];
}

// ---------------------------------------------------------------------------
// Launch
// ---------------------------------------------------------------------------
static int find_size(const int* s, int n, int want, int occ) {
    int c = 0;
    for (int i = 0; i < n; i++)
        if (s[i] == want) { if (c == occ) return i; c++; }
    return 0;
}

extern "C" void kernel_launch(void* const* d_in, const int* in_sizes, int n_in,
                              void* d_out, int out_size)
{
    const int ix    = find_size(in_sizes, n_in, 3325000, 0);
    const int iei   = find_size(in_sizes, n_in, 200000, 0);
    const int iea   = find_size(in_sizes, n_in, 1400000, 0);
    const int ibat  = find_size(in_sizes, n_in, 25000, 0);
    const int iWei  = find_size(in_sizes, n_in, 75264, 0);
    const int iWcv  = find_size(in_sizes, n_in, 1048576, 0);
    const int ibcv  = find_size(in_sizes, n_in, 2048, 0);
    const int iWe2n = find_size(in_sizes, n_in, 330240, 0);
    const int iWf1  = find_size(in_sizes, n_in, 262144, 0);
    const int ibf2  = find_size(in_sizes, n_in, 1, 0);
    int o512[4];
    for (int k = 0; k < 4; k++) o512[k] = find_size(in_sizes, n_in, 512, k);
    int ibei, ibe2n, ibf1, iWf2;
    if (in_sizes[0] == 3325000) {
        ibei = o512[0]; ibe2n = o512[1]; ibf1 = o512[2]; iWf2 = o512[3];
    } else if (in_sizes[0] == 1048576) {
        iWf2 = o512[0]; ibe2n = o512[1]; ibei = o512[2]; ibf1 = o512[3];
    } else if (in_sizes[0] == 2048) {
        ibe2n = o512[0]; ibei = o512[1]; ibf1 = o512[2]; iWf2 = o512[3];
    } else {
        ibei = o512[0]; ibe2n = o512[1]; ibf1 = o512[2]; iWf2 = o512[3];
    }

    const float* x     = (const float*)d_in[ix];
    const int*   ei    = (const int*)d_in[iei];
    const float* ea    = (const float*)d_in[iea];
    const int*   bat   = (const int*)d_in[ibat];
    const float* W_ei  = (const float*)d_in[iWei];
    const float* b_ei  = (const float*)d_in[ibei];
    const float* W_cv  = (const float*)d_in[iWcv];
    const float* b_cv  = (const float*)d_in[ibcv];
    const float* W_e2n = (const float*)d_in[iWe2n];
    const float* b_e2n = (const float*)d_in[ibe2n];
    const float* W_f1  = (const float*)d_in[iWf1];
    const float* b_f1  = (const float*)d_in[ibf1];
    const float* W_f2  = (const float*)d_in[iWf2];
    const float* b_f2  = (const float*)d_in[ibf2];
    float* out = (float*)d_out;

    float *h0, *hA, *hB, *aA, *aB, *pool;
    cudaGetSymbolAddress((void**)&h0,   g_h0);
    cudaGetSymbolAddress((void**)&hA,   g_hA);
    cudaGetSymbolAddress((void**)&hB,   g_hB);
    cudaGetSymbolAddress((void**)&aA,   g_aA);
    cudaGetSymbolAddress((void**)&aB,   g_aB);
    cudaGetSymbolAddress((void**)&pool, g_pool);

    const int a_n4 = (N_NODES * HID) / 4;
    const int p_n4 = (NG * HID) / 4;
    dim3 gE(HID / 128, (E_EDGES + 127) / 128);   // (4, 782)
    dim3 gN(HID / 128, (N_NODES + 127) / 128);   // (4, 196)

    // aA, pool, and layer-0 target aB zeroed up front (aB off critical path)
    zero_kernel<<<(a_n4 + 255) / 256, 256>>>((float4*)aA, a_n4);
    zero_kernel<<<(p_n4 + 255) / 256, 256>>>((float4*)pool, p_n4);
    zero_kernel<<<(a_n4 + 255) / 256, 256>>>((float4*)aB, a_n4);

    // Edge init, factored: X' = x@W1 + b (node-level), then combine per edge
    xproj_kernel<<<gN, 256>>>(x, W_ei, b_ei, hB);
    edge_combine_kernel<<<E_EDGES / 8, 256>>>(hB, ea, W_ei + (size_t)FN * HID, ei);

    // layer 0: h0 -> hA ; aA -> aB
    conv_kernel<<<gE, 256>>>(h0, aA, hA, aB, W_cv + 0 * HID * HID, b_cv + 0 * HID, ei);
    // layer 1: hA -> hB ; aB -> aA
    zero_kernel<<<(a_n4 + 255) / 256, 256>>>((float4*)aA, a_n4);
    conv_kernel<<<gE, 256>>>(hA, aB, hB, aA, W_cv + 1 * HID * HID, b_cv + 1 * HID, ei);
    // layer 2: hB -> hA ; aA -> aB
    zero_kernel<<<(a_n4 + 255) / 256, 256>>>((float4*)aB, a_n4);
    conv_kernel<<<gE, 256>>>(hB, aA, hA, aB, W_cv + 2 * HID * HID, b_cv + 2 * HID, ei);
    // layer 3: hA -> hB ; aB -> aA   (aA ends as s)
    zero_kernel<<<(a_n4 + 255) / 256, 256>>>((float4*)aA, a_n4);
    conv_kernel<<<gE, 256>>>(hA, aB, hB, aA, W_cv + 3 * HID * HID, b_cv + 3 * HID, ei);

    e2n_kernel<<<gN, 256>>>(x, aA, W_e2n, b_e2n, bat);
    ffn_kernel<<<NG / 8, 256>>>(W_f1, b_f1, W_f2, b_f2, out);

    (void)out_size;
}

// round 16
// speedup vs baseline: 1.0535x; 1.0222x over previous
#include <cuda_runtime.h>
#include <cstdint>
#include <cstddef>

// Problem constants
#define E_EDGES 100000
#define N_NODES 25000
#define HID 512
#define NG 2048
#define FN 133
#define FE 14
#define KE2N 645

// ---------------------------------------------------------------------------
// Scratch (device globals)
// ---------------------------------------------------------------------------
__device__ float g_h0[(size_t)E_EDGES * HID];
__device__ float g_hA[(size_t)E_EDGES * HID];
__device__ float g_hB[(size_t)E_EDGES * HID];   // first 25k rows reused as X' in edge phase
__device__ float g_aA[(size_t)N_NODES * HID];
__device__ float g_aB[(size_t)N_NODES * HID];
__device__ float g_pool[(size_t)NG * HID];

// ---------------------------------------------------------------------------
// Helpers
// ---------------------------------------------------------------------------
__device__ __forceinline__ void red_add_v4(float* addr, float x, float y, float z, float w) {
    asm volatile("red.global.add.v4.f32 [%0], {%1,%2,%3,%4};"
                 :: "l"(addr), "f"(x), "f"(y), "f"(z), "f"(w) : "memory");
}

// ---------------------------------------------------------------------------
// Zero fill
// ---------------------------------------------------------------------------
__global__ void zero_kernel(float4* __restrict__ p, int n4) {
    int i = blockIdx.x * blockDim.x + threadIdx.x;
    int stride = gridDim.x * blockDim.x;
    for (; i < n4; i += stride) p[i] = make_float4(0.f, 0.f, 0.f, 0.f);
}

// ---------------------------------------------------------------------------
// Node projection: X'[n] = x[n] @ W1 + b   (M=25000, K=133 pad 136, N=512)
// ---------------------------------------------------------------------------
__global__ __launch_bounds__(256, 2)
void xproj_kernel(const float* __restrict__ x, const float* __restrict__ W,
                  const float* __restrict__ bias, float* __restrict__ Xp)
{
    __shared__ float As[8][132];
    __shared__ float Bs[8][128];
    const int tid = threadIdx.x;
    const int tx = tid & 15, ty = tid >> 4;
    const int bm = blockIdx.y * 128;
    const int bn = blockIdx.x * 128;

    const int arow = tid >> 1;
    const int ac4  = (tid & 1) * 4;
    const int am   = bm + arow;
    const bool aValid = (am < N_NODES);

    const int brow = tid >> 5;
    const int bc4  = (tid & 31) * 4;

    float acc[8][8];
    #pragma unroll
    for (int i = 0; i < 8; i++)
        #pragma unroll
        for (int j = 0; j < 8; j++) acc[i][j] = 0.f;

    for (int k0 = 0; k0 < 136; k0 += 8) {
        #pragma unroll
        for (int i = 0; i < 4; i++) {
            int k = k0 + ac4 + i;
            float v = 0.f;
            if (aValid && k < FN) v = x[(size_t)am * FN + k];
            As[ac4 + i][arow] = v;
        }
        int kRow = k0 + brow;
        float4 bv = make_float4(0.f, 0.f, 0.f, 0.f);
        if (kRow < FN) bv = *(const float4*)(W + (size_t)kRow * HID + bn + bc4);
        *(float4*)&Bs[brow][bc4] = bv;
        __syncthreads();

        #pragma unroll
        for (int kk = 0; kk < 8; kk++) {
            float ar[8], br[8];
            #pragma unroll
            for (int i = 0; i < 8; i++) ar[i] = As[kk][ty * 8 + i];
            #pragma unroll
            for (int j = 0; j < 8; j++) br[j] = Bs[kk][tx * 8 + j];
            #pragma unroll
            for (int i = 0; i < 8; i++)
                #pragma unroll
                for (int j = 0; j < 8; j++) acc[i][j] += ar[i] * br[j];
        }
        __syncthreads();
    }

    const int n0 = bn + tx * 8;
    float bres[8];
    #pragma unroll
    for (int j = 0; j < 8; j++) bres[j] = bias[n0 + j];

    #pragma unroll
    for (int i = 0; i < 8; i++) {
        int m = bm + ty * 8 + i;
        if (m < N_NODES) {
            float* xo = Xp + (size_t)m * HID + n0;
            *(float4*)(xo)     = make_float4(acc[i][0] + bres[0], acc[i][1] + bres[1],
                                             acc[i][2] + bres[2], acc[i][3] + bres[3]);
            *(float4*)(xo + 4) = make_float4(acc[i][4] + bres[4], acc[i][5] + bres[5],
                                             acc[i][6] + bres[6], acc[i][7] + bres[7]);
        }
    }
}

// ---------------------------------------------------------------------------
// Edge combine (R10-proven, one warp per edge):
//   h0[e] = relu(X'[row[e]] + ea[e] @ W2);  aA[col[e]] += h0[e]
// ---------------------------------------------------------------------------
__global__ __launch_bounds__(256)
void edge_combine_kernel(const float* __restrict__ Xp, const float* __restrict__ ea,
                         const float* __restrict__ W2, const int* __restrict__ ei)
{
    __shared__ float W2s[FE * HID];   // 28 KB
    const int tid = threadIdx.x;
    for (int i = tid; i < FE * HID; i += 256) W2s[i] = W2[i];
    __syncthreads();

    const int w = tid >> 5;
    const int lane = tid & 31;
    const int e = blockIdx.x * 8 + w;     // grid 12500 * 8 = 100000 exact

    const int r = ei[e];
    const int c = ei[E_EDGES + e];
    float ear[FE];
    #pragma unroll
    for (int k = 0; k < FE; k++) ear[k] = ea[(size_t)e * FE + k];

    const float* xp = Xp + (size_t)r * HID;
    float* h0p = g_h0 + (size_t)e * HID;
    float* aop = g_aA + (size_t)c * HID;

    #pragma unroll
    for (int i = 0; i < 4; i++) {
        const int c4 = i * 128 + lane * 4;
        float4 acc = *(const float4*)(xp + c4);
        #pragma unroll
        for (int k = 0; k < FE; k++) {
            float4 w4 = *(const float4*)(W2s + k * HID + c4);
            acc.x += ear[k] * w4.x;  acc.y += ear[k] * w4.y;
            acc.z += ear[k] * w4.z;  acc.w += ear[k] * w4.w;
        }
        acc.x = acc.x > 0.f ? acc.x : 0.f;
        acc.y = acc.y > 0.f ? acc.y : 0.f;
        acc.z = acc.z > 0.f ? acc.z : 0.f;
        acc.w = acc.w > 0.f ? acc.w : 0.f;
        *(float4*)(h0p + c4) = acc;
        red_add_v4(aop + c4, acc.x, acc.y, acc.z, acc.w);
    }
}

// ---------------------------------------------------------------------------
// Conv layer (R10-proven, 128x128, 256 threads):
//   h_out[e] = relu((a[row[e]] - h[e^1]) @ W + b + h0[e]); a_out[col[e]] += h_out
// ---------------------------------------------------------------------------
__global__ __launch_bounds__(256, 2)
void conv_kernel(const float* __restrict__ h_in, const float* __restrict__ a_in,
                 float* __restrict__ h_out, float* __restrict__ a_out,
                 const float* __restrict__ W, const float* __restrict__ bias,
                 const int* __restrict__ ei)
{
    __shared__ float As[8][132];
    __shared__ float Bs[8][128];
    const int tid = threadIdx.x;
    const int tx = tid & 15, ty = tid >> 4;
    const int bm = blockIdx.y * 128;
    const int bn = blockIdx.x * 128;

    const int arow = tid >> 1;
    const int ac4  = (tid & 1) * 4;
    const int am   = bm + arow;
    const bool aValid = (am < E_EDGES);
    const int r = aValid ? ei[am] : 0;
    const float* a_src = a_in + (size_t)r * HID + ac4;
    const float* h_src = h_in + (size_t)(am ^ 1) * HID + ac4;

    const int brow = tid >> 5;
    const int bc4  = (tid & 31) * 4;
    const float* w_src = W + (size_t)brow * HID + bn + bc4;

    float acc[8][8];
    #pragma unroll
    for (int i = 0; i < 8; i++)
        #pragma unroll
        for (int j = 0; j < 8; j++) acc[i][j] = 0.f;

    for (int k0 = 0; k0 < HID; k0 += 8) {
        float4 av = make_float4(0.f, 0.f, 0.f, 0.f);
        if (aValid) {
            float4 aa = *(const float4*)(a_src + k0);
            float4 hh = *(const float4*)(h_src + k0);
            av.x = aa.x - hh.x; av.y = aa.y - hh.y;
            av.z = aa.z - hh.z; av.w = aa.w - hh.w;
        }
        As[ac4 + 0][arow] = av.x;
        As[ac4 + 1][arow] = av.y;
        As[ac4 + 2][arow] = av.z;
        As[ac4 + 3][arow] = av.w;
        *(float4*)&Bs[brow][bc4] = *(const float4*)(w_src + (size_t)k0 * HID);
        __syncthreads();

        #pragma unroll
        for (int kk = 0; kk < 8; kk++) {
            float ar[8], br[8];
            #pragma unroll
            for (int i = 0; i < 8; i++) ar[i] = As[kk][ty * 8 + i];
            #pragma unroll
            for (int j = 0; j < 8; j++) br[j] = Bs[kk][tx * 8 + j];
            #pragma unroll
            for (int i = 0; i < 8; i++)
                #pragma unroll
                for (int j = 0; j < 8; j++) acc[i][j] += ar[i] * br[j];
        }
        __syncthreads();
    }

    const int n0 = bn + tx * 8;
    float bres[8];
    #pragma unroll
    for (int j = 0; j < 8; j++) bres[j] = bias[n0 + j];

    #pragma unroll
    for (int i = 0; i < 8; i++) {
        int m = bm + ty * 8 + i;
        if (m < E_EDGES) {
            const float* h0r = g_h0 + (size_t)m * HID + n0;
            float4 r0 = *(const float4*)(h0r);
            float4 r1 = *(const float4*)(h0r + 4);
            float v[8];
            v[0] = acc[i][0] + bres[0] + r0.x; v[1] = acc[i][1] + bres[1] + r0.y;
            v[2] = acc[i][2] + bres[2] + r0.z; v[3] = acc[i][3] + bres[3] + r0.w;
            v[4] = acc[i][4] + bres[4] + r1.x; v[5] = acc[i][5] + bres[5] + r1.y;
            v[6] = acc[i][6] + bres[6] + r1.z; v[7] = acc[i][7] + bres[7] + r1.w;
            #pragma unroll
            for (int j = 0; j < 8; j++) v[j] = v[j] > 0.f ? v[j] : 0.f;
            float* ho = h_out + (size_t)m * HID + n0;
            *(float4*)(ho)     = make_float4(v[0], v[1], v[2], v[3]);
            *(float4*)(ho + 4) = make_float4(v[4], v[5], v[6], v[7]);
            int c = ei[E_EDGES + m];
            float* ao = a_out + (size_t)c * HID + n0;
            red_add_v4(ao,     v[0], v[1], v[2], v[3]);
            red_add_v4(ao + 4, v[4], v[5], v[6], v[7]);
        }
    }
}

// ---------------------------------------------------------------------------
// Edge-to-node, two-phase K loop:
//   phase 1: s-part (K=512, clean float4 feed, W rows FN..FN+511)
//   phase 2: x-part (K=133 pad 136, guarded feed, W rows 0..132)
//   hn[n] = relu([x[n],s[n]] @ W_e2n + b); pool[batch[n]] += hn
// ---------------------------------------------------------------------------
__global__ __launch_bounds__(256, 2)
void e2n_kernel(const float* __restrict__ x, const float* __restrict__ s,
                const float* __restrict__ W, const float* __restrict__ bias,
                const int* __restrict__ bat)
{
    __shared__ float As[8][132];
    __shared__ float Bs[8][128];
    const int tid = threadIdx.x;
    const int tx = tid & 15, ty = tid >> 4;
    const int bm = blockIdx.y * 128;
    const int bn = blockIdx.x * 128;

    const int arow = tid >> 1;
    const int ac4  = (tid & 1) * 4;
    const int am   = bm + arow;
    const bool aValid = (am < N_NODES);
    const float* s_src = s + (size_t)am * HID + ac4;

    const int brow = tid >> 5;
    const int bc4  = (tid & 31) * 4;

    float acc[8][8];
    #pragma unroll
    for (int i = 0; i < 8; i++)
        #pragma unroll
        for (int j = 0; j < 8; j++) acc[i][j] = 0.f;

    // ---- Phase 1: s-part (clean vectorized feed) ----
    for (int k0 = 0; k0 < HID; k0 += 8) {
        float4 av = make_float4(0.f, 0.f, 0.f, 0.f);
        if (aValid) av = *(const float4*)(s_src + k0);
        As[ac4 + 0][arow] = av.x;
        As[ac4 + 1][arow] = av.y;
        As[ac4 + 2][arow] = av.z;
        As[ac4 + 3][arow] = av.w;
        *(float4*)&Bs[brow][bc4] =
            *(const float4*)(W + (size_t)(FN + k0 + brow) * HID + bn + bc4);
        __syncthreads();

        #pragma unroll
        for (int kk = 0; kk < 8; kk++) {
            float ar[8], br[8];
            #pragma unroll
            for (int i = 0; i < 8; i++) ar[i] = As[kk][ty * 8 + i];
            #pragma unroll
            for (int j = 0; j < 8; j++) br[j] = Bs[kk][tx * 8 + j];
            #pragma unroll
            for (int i = 0; i < 8; i++)
                #pragma unroll
                for (int j = 0; j < 8; j++) acc[i][j] += ar[i] * br[j];
        }
        __syncthreads();
    }

    // ---- Phase 2: x-part (guarded feed, 17 iters) ----
    for (int k0 = 0; k0 < 136; k0 += 8) {
        #pragma unroll
        for (int i = 0; i < 4; i++) {
            int k = k0 + ac4 + i;
            float v = 0.f;
            if (aValid && k < FN) v = x[(size_t)am * FN + k];
            As[ac4 + i][arow] = v;
        }
        int kRow = k0 + brow;
        float4 bv = make_float4(0.f, 0.f, 0.f, 0.f);
        if (kRow < FN) bv = *(const float4*)(W + (size_t)kRow * HID + bn + bc4);
        *(float4*)&Bs[brow][bc4] = bv;
        __syncthreads();

        #pragma unroll
        for (int kk = 0; kk < 8; kk++) {
            float ar[8], br[8];
            #pragma unroll
            for (int i = 0; i < 8; i++) ar[i] = As[kk][ty * 8 + i];
            #pragma unroll
            for (int j = 0; j < 8; j++) br[j] = Bs[kk][tx * 8 + j];
            #pragma unroll
            for (int i = 0; i < 8; i++)
                #pragma unroll
                for (int j = 0; j < 8; j++) acc[i][j] += ar[i] * br[j];
        }
        __syncthreads();
    }

    const int n0 = bn + tx * 8;
    float bres[8];
    #pragma unroll
    for (int j = 0; j < 8; j++) bres[j] = bias[n0 + j];

    #pragma unroll
    for (int i = 0; i < 8; i++) {
        int m = bm + ty * 8 + i;
        if (m < N_NODES) {
            float v[8];
            #pragma unroll
            for (int j = 0; j < 8; j++) {
                float t = acc[i][j] + bres[j];
                v[j] = t > 0.f ? t : 0.f;
            }
            int g = bat[m];
            float* po = g_pool + (size_t)g * HID + n0;
            red_add_v4(po,     v[0], v[1], v[2], v[3]);
            red_add_v4(po + 4, v[4], v[5], v[6], v[7]);
        }
    }
}

// ---------------------------------------------------------------------------
// FFN head
// ---------------------------------------------------------------------------
__global__ __launch_bounds__(256)
void ffn_kernel(const float* __restrict__ W1, const float* __restrict__ b1,
                const float* __restrict__ W2, const float* __restrict__ b2,
                float* __restrict__ out)
{
    __shared__ float P[8][512];
    __shared__ float R[8 * 256];
    const int tid = threadIdx.x;
    const int g0 = blockIdx.x * 8;

    for (int i = tid; i < 8 * 512; i += 256) {
        int t = i >> 9, k = i & 511;
        P[t][k] = g_pool[(size_t)(g0 + t) * HID + k];
    }
    __syncthreads();

    float partial[8];
    #pragma unroll
    for (int t = 0; t < 8; t++) partial[t] = 0.f;

    #pragma unroll
    for (int rep = 0; rep < 2; rep++) {
        const int j = tid + rep * 256;
        float acc[8];
        #pragma unroll
        for (int t = 0; t < 8; t++) acc[t] = 0.f;
        const float bb = b1[j];
        const float w2 = W2[j];
        for (int k = 0; k < 512; k++) {
            float w = W1[(size_t)k * 512 + j];
            #pragma unroll
            for (int t = 0; t < 8; t++) acc[t] += P[t][k] * w;
        }
        #pragma unroll
        for (int t = 0; t < 8; t++) {
            float h = acc[t] + bb;
            h = h > 0.f ? h : 0.f;
            partial[t] += h * w2;
        }
    }

    #pragma unroll
    for (int t = 0; t < 8; t++) R[t * 256 + tid] = partial[t];
    __syncthreads();
    for (int srd = 128; srd > 0; srd >>= 1) {
        if (tid < srd) {
            #pragma unroll
            for (int t = 0; t < 8; t++) R[t * 256 + tid] += R[t * 256 + tid + srd];
        }
        __syncthreads();
    }
    if (tid < 8) out[g0 + tid] = R[tid * 256] + b2[0];
}

// ---------------------------------------------------------------------------
// Launch
// ---------------------------------------------------------------------------
static int find_size(const int* s, int n, int want, int occ) {
    int c = 0;
    for (int i = 0; i < n; i++)
        if (s[i] == want) { if (c == occ) return i; c++; }
    return 0;
}

extern "C" void kernel_launch(void* const* d_in, const int* in_sizes, int n_in,
                              void* d_out, int out_size)
{
    const int ix    = find_size(in_sizes, n_in, 3325000, 0);
    const int iei   = find_size(in_sizes, n_in, 200000, 0);
    const int iea   = find_size(in_sizes, n_in, 1400000, 0);
    const int ibat  = find_size(in_sizes, n_in, 25000, 0);
    const int iWei  = find_size(in_sizes, n_in, 75264, 0);
    const int iWcv  = find_size(in_sizes, n_in, 1048576, 0);
    const int ibcv  = find_size(in_sizes, n_in, 2048, 0);
    const int iWe2n = find_size(in_sizes, n_in, 330240, 0);
    const int iWf1  = find_size(in_sizes, n_in, 262144, 0);
    const int ibf2  = find_size(in_sizes, n_in, 1, 0);
    int o512[4];
    for (int k = 0; k < 4; k++) o512[k] = find_size(in_sizes, n_in, 512, k);
    int ibei, ibe2n, ibf1, iWf2;
    if (in_sizes[0] == 3325000) {
        ibei = o512[0]; ibe2n = o512[1]; ibf1 = o512[2]; iWf2 = o512[3];
    } else if (in_sizes[0] == 1048576) {
        iWf2 = o512[0]; ibe2n = o512[1]; ibei = o512[2]; ibf1 = o512[3];
    } else if (in_sizes[0] == 2048) {
        ibe2n = o512[0]; ibei = o512[1]; ibf1 = o512[2]; iWf2 = o512[3];
    } else {
        ibei = o512[0]; ibe2n = o512[1]; ibf1 = o512[2]; iWf2 = o512[3];
    }

    const float* x     = (const float*)d_in[ix];
    const int*   ei    = (const int*)d_in[iei];
    const float* ea    = (const float*)d_in[iea];
    const int*   bat   = (const int*)d_in[ibat];
    const float* W_ei  = (const float*)d_in[iWei];
    const float* b_ei  = (const float*)d_in[ibei];
    const float* W_cv  = (const float*)d_in[iWcv];
    const float* b_cv  = (const float*)d_in[ibcv];
    const float* W_e2n = (const float*)d_in[iWe2n];
    const float* b_e2n = (const float*)d_in[ibe2n];
    const float* W_f1  = (const float*)d_in[iWf1];
    const float* b_f1  = (const float*)d_in[ibf1];
    const float* W_f2  = (const float*)d_in[iWf2];
    const float* b_f2  = (const float*)d_in[ibf2];
    float* out = (float*)d_out;

    float *h0, *hA, *hB, *aA, *aB, *pool;
    cudaGetSymbolAddress((void**)&h0,   g_h0);
    cudaGetSymbolAddress((void**)&hA,   g_hA);
    cudaGetSymbolAddress((void**)&hB,   g_hB);
    cudaGetSymbolAddress((void**)&aA,   g_aA);
    cudaGetSymbolAddress((void**)&aB,   g_aB);
    cudaGetSymbolAddress((void**)&pool, g_pool);

    const int a_n4 = (N_NODES * HID) / 4;
    const int p_n4 = (NG * HID) / 4;
    dim3 gE(HID / 128, (E_EDGES + 127) / 128);   // (4, 782)
    dim3 gN(HID / 128, (N_NODES + 127) / 128);   // (4, 196)

    // aA, pool, and layer-0 target aB zeroed up front (aB off critical path)
    zero_kernel<<<(a_n4 + 255) / 256, 256>>>((float4*)aA, a_n4);
    zero_kernel<<<(p_n4 + 255) / 256, 256>>>((float4*)pool, p_n4);
    zero_kernel<<<(a_n4 + 255) / 256, 256>>>((float4*)aB, a_n4);

    // Edge init, factored: X' = x@W1 + b (node-level), then combine per edge
    xproj_kernel<<<gN, 256>>>(x, W_ei, b_ei, hB);
    edge_combine_kernel<<<E_EDGES / 8, 256>>>(hB, ea, W_ei + (size_t)FN * HID, ei);

    // layer 0: h0 -> hA ; aA -> aB
    conv_kernel<<<gE, 256>>>(h0, aA, hA, aB, W_cv + 0 * HID * HID, b_cv + 0 * HID, ei);
    // layer 1: hA -> hB ; aB -> aA
    zero_kernel<<<(a_n4 + 255) / 256, 256>>>((float4*)aA, a_n4);
    conv_kernel<<<gE, 256>>>(hA, aB, hB, aA, W_cv + 1 * HID * HID, b_cv + 1 * HID, ei);
    // layer 2: hB -> hA ; aA -> aB
    zero_kernel<<<(a_n4 + 255) / 256, 256>>>((float4*)aB, a_n4);
    conv_kernel<<<gE, 256>>>(hB, aA, hA, aB, W_cv + 2 * HID * HID, b_cv + 2 * HID, ei);
    // layer 3: hA -> hB ; aB -> aA   (aA ends as s)
    zero_kernel<<<(a_n4 + 255) / 256, 256>>>((float4*)aA, a_n4);
    conv_kernel<<<gE, 256>>>(hA, aB, hB, aA, W_cv + 3 * HID * HID, b_cv + 3 * HID, ei);

    e2n_kernel<<<gN, 256>>>(x, aA, W_e2n, b_e2n, bat);
    ffn_kernel<<<NG / 8, 256>>>(W_f1, b_f1, W_f2, b_f2, out);

    (void)out_size;
}